// round 9
// baseline (speedup 1.0000x reference)
#include <cuda_runtime.h>
#include <cuda_bf16.h>
#include <cstdint>
#include <math.h>

#define MAXN 50000
#define FDIM 128
#define TILE 128
#define NTH  512
#define PLANE ((size_t)MAXN * FDIM)

// padded bf16 planes: row stride 136 bf16 = 272 B (ldmatrix conflict-free)
#define LDSB 272u
#define PLB  34816u
#define AHO 0u
#define ALO PLB
#define B0H (2u*PLB)
#define B0L (3u*PLB)
#define B1H (4u*PLB)
#define B1L (5u*PLB)
#define SMSZ6 (6u*PLB)            // 208896
#define VBH (2u*PLB)
#define VBL (3u*PLB)
#define VST (4u*PLB)
#define SMSZV (4u*PLB + 65536u)   // 204800

// -------- scratch --------
__device__ float g_M0[MAXN * FDIM];
__device__ float g_M1[3][MAXN * FDIM];
__device__ float g_M2[3][MAXN * FDIM];
__device__ float g_M3[3][MAXN * FDIM];
__device__ float g_ms[MAXN * FDIM];
__device__ float g_mv[3][MAXN * FDIM];
__device__ __nv_bfloat16 g_Wimg[8][32768];   // [hi 16384 | lo 16384], [out][in]

// ================= helpers =================
__device__ __forceinline__ uint32_t smem_u32(const void* p) {
    uint32_t a;
    asm("{ .reg .u64 t; cvta.to.shared.u64 t, %1; cvt.u32.u64 %0, t; }" : "=r"(a) : "l"(p));
    return a;
}
__device__ __forceinline__ void cpa16(uint32_t dst, const void* src) {
    asm volatile("cp.async.cg.shared.global [%0], [%1], 16;" :: "r"(dst), "l"(src));
}
__device__ __forceinline__ void cpa_commit() { asm volatile("cp.async.commit_group;"); }
template <int K> __device__ __forceinline__ void cpa_wait() {
    asm volatile("cp.async.wait_group %0;" :: "n"(K));
}
__device__ __forceinline__ void ldm4(uint32_t* r, uint32_t addr) {
    asm volatile("ldmatrix.sync.aligned.m8n8.x4.shared.b16 {%0,%1,%2,%3}, [%4];"
                 : "=r"(r[0]), "=r"(r[1]), "=r"(r[2]), "=r"(r[3]) : "r"(addr));
}
__device__ __forceinline__ void mma16816(float* c, const uint32_t* a, uint32_t b0, uint32_t b1) {
    asm volatile(
        "mma.sync.aligned.m16n8k16.row.col.f32.bf16.bf16.f32 "
        "{%0,%1,%2,%3}, {%4,%5,%6,%7}, {%8,%9}, {%0,%1,%2,%3};"
        : "+f"(c[0]), "+f"(c[1]), "+f"(c[2]), "+f"(c[3])
        : "r"(a[0]), "r"(a[1]), "r"(a[2]), "r"(a[3]), "r"(b0), "r"(b1));
}
__device__ __forceinline__ void split1(float x, unsigned short& h, unsigned short& l) {
    __nv_bfloat16 hb = __float2bfloat16(x);
    float r = x - __bfloat162float(hb);
    __nv_bfloat16 lb = __float2bfloat16(r);
    h = *(unsigned short*)&hb;
    l = *(unsigned short*)&lb;
}
__device__ __forceinline__ uint32_t pack2(unsigned short a, unsigned short b) {
    return (uint32_t)a | ((uint32_t)b << 16);
}
__device__ __forceinline__ float sigf(float x) { return 1.f / (1.f + __expf(-x)); }

__device__ __forceinline__ void prefetch_B(uint32_t sb, uint32_t bho, uint32_t blo,
                                           const __nv_bfloat16* __restrict__ img) {
    for (int i = threadIdx.x; i < 4096; i += NTH) {
        int half = i >> 11, idx = i & 2047;
        uint32_t r = (uint32_t)(idx >> 4), q = (uint32_t)(idx & 15);
        uint32_t dst = sb + (half ? blo : bho) + r * LDSB + q * 16u;
        cpa16(dst, (const uint4*)(img + half * 16384) + idx);
    }
    cpa_commit();
}

__device__ __forceinline__ void load_split_A(char* sm, const float* __restrict__ src,
                                             int n0, int N) {
    for (int i = threadIdx.x; i < TILE * 16; i += NTH) {
        uint32_t r = (uint32_t)(i >> 4), q = (uint32_t)(i & 15);
        float4 v0 = make_float4(0.f, 0.f, 0.f, 0.f), v1 = v0;
        if (n0 + (int)r < N) {
            const float* p = src + (size_t)(n0 + r) * FDIM + q * 8;
            v0 = *(const float4*)p;
            v1 = *(const float4*)(p + 4);
        }
        unsigned short h[8], l[8];
        split1(v0.x, h[0], l[0]); split1(v0.y, h[1], l[1]);
        split1(v0.z, h[2], l[2]); split1(v0.w, h[3], l[3]);
        split1(v1.x, h[4], l[4]); split1(v1.y, h[5], l[5]);
        split1(v1.z, h[6], l[6]); split1(v1.w, h[7], l[7]);
        uint32_t off = r * LDSB + q * 16u;
        *(uint4*)(sm + AHO + off) = make_uint4(pack2(h[0], h[1]), pack2(h[2], h[3]),
                                               pack2(h[4], h[5]), pack2(h[6], h[7]));
        *(uint4*)(sm + ALO + off) = make_uint4(pack2(l[0], l[1]), pack2(l[2], l[3]),
                                               pack2(l[4], l[5]), pack2(l[6], l[7]));
    }
}

// ---- 3-term split GEMM, 16 warps: grid 4(M)x4(N); warp tile 32x32 ----
// per kc: 8 ldm4 + 24 mma; acc[mt2][nidx4][4]
__device__ __forceinline__ void gemm3(uint32_t sb, uint32_t bho, uint32_t blo,
                                      int warpM, int warpN, int lane, float acc[2][4][4]) {
    uint32_t rowA = (uint32_t)(warpM * 32 + (lane & 15)) * LDSB;
    uint32_t rowB = (uint32_t)(warpN * 32 + (lane & 15)) * LDSB;
    uint32_t kh = (uint32_t)((lane >> 4) * 8) * 2u;
#pragma unroll
    for (int kc = 0; kc < 8; ++kc) {
        uint32_t kof = kh + (uint32_t)kc * 32u;
        uint32_t ah[2][4], al[2][4], bh[2][4], bl[2][4];
#pragma unroll
        for (int mt = 0; mt < 2; ++mt) {
            uint32_t a = rowA + (uint32_t)(mt * 16) * LDSB + kof;
            ldm4(ah[mt], sb + AHO + a);
            ldm4(al[mt], sb + ALO + a);
        }
#pragma unroll
        for (int nt = 0; nt < 2; ++nt) {
            uint32_t b = rowB + (uint32_t)(nt * 16) * LDSB + kof;
            ldm4(bh[nt], sb + bho + b);
            ldm4(bl[nt], sb + blo + b);
        }
#pragma unroll
        for (int mt = 0; mt < 2; ++mt)
#pragma unroll
            for (int nt = 0; nt < 2; ++nt) {
                mma16816(acc[mt][nt * 2 + 0], ah[mt], bh[nt][0], bh[nt][2]);
                mma16816(acc[mt][nt * 2 + 1], ah[mt], bh[nt][1], bh[nt][3]);
                mma16816(acc[mt][nt * 2 + 0], ah[mt], bl[nt][0], bl[nt][2]);
                mma16816(acc[mt][nt * 2 + 1], ah[mt], bl[nt][1], bl[nt][3]);
                mma16816(acc[mt][nt * 2 + 0], al[mt], bh[nt][0], bh[nt][2]);
                mma16816(acc[mt][nt * 2 + 1], al[mt], bh[nt][1], bh[nt][3]);
            }
    }
}
__device__ __forceinline__ void zero_acc(float acc[2][4][4]) {
#pragma unroll
    for (int m = 0; m < 2; ++m)
#pragma unroll
        for (int n = 0; n < 4; ++n)
#pragma unroll
            for (int j = 0; j < 4; ++j) acc[m][n][j] = 0.f;
}

// ================= prep =================
struct WPtrs { const float* p[8]; };
__global__ void prep_weights(WPtrs wp) {
    int w = blockIdx.x;
    const float* src = wp.p[w];
    __nv_bfloat16* hi = g_Wimg[w];
    __nv_bfloat16* lo = g_Wimg[w] + 16384;
    for (int i = threadIdx.x; i < 16384; i += blockDim.x) {
        int k = i >> 7, g = i & 127;
        unsigned short h, l;
        split1(src[i], h, l);
        hi[g * 128 + k] = *(__nv_bfloat16*)&h;
        lo[g * 128 + k] = *(__nv_bfloat16*)&l;
    }
}

// ================= kernels =================
__global__ void __launch_bounds__(NTH) dense2_mma_kernel(
    const float* __restrict__ in,
    const __nv_bfloat16* __restrict__ img1, const float* __restrict__ b1,
    const __nv_bfloat16* __restrict__ img2, const float* __restrict__ b2,
    float* __restrict__ out, int N) {
    extern __shared__ char sm[];
    int tid = threadIdx.x, wid = tid >> 5, lane = tid & 31;
    int warpM = wid >> 2, warpN = wid & 3;
    int n0 = blockIdx.x * TILE;
    uint32_t sb = smem_u32(sm);
    int r0 = warpM * 32 + (lane >> 2);
    int c0b = warpN * 32 + (lane & 3) * 2;

    prefetch_B(sb, B0H, B0L, img1);
    prefetch_B(sb, B1H, B1L, img2);
    load_split_A(sm, in, n0, N);
    cpa_wait<1>();
    __syncthreads();

    float acc[2][4][4];
    zero_acc(acc);
    gemm3(sb, B0H, B0L, warpM, warpN, lane, acc);
    __syncthreads();

#pragma unroll
    for (int mt = 0; mt < 2; ++mt)
#pragma unroll
        for (int nidx = 0; nidx < 4; ++nidx) {
            int c = c0b + nidx * 8;
            float2 bb = *(const float2*)(b1 + c);
#pragma unroll
            for (int hrow = 0; hrow < 2; ++hrow) {
                uint32_t r = (uint32_t)(r0 + mt * 16 + hrow * 8);
                float x = acc[mt][nidx][hrow * 2 + 0] + bb.x;
                float y = acc[mt][nidx][hrow * 2 + 1] + bb.y;
                x *= sigf(x); y *= sigf(y);
                unsigned short hx, lx, hy, ly;
                split1(x, hx, lx); split1(y, hy, ly);
                uint32_t off = r * LDSB + (uint32_t)c * 2u;
                *(uint32_t*)(sm + AHO + off) = pack2(hx, hy);
                *(uint32_t*)(sm + ALO + off) = pack2(lx, ly);
            }
        }
    cpa_wait<0>();
    __syncthreads();

    zero_acc(acc);
    gemm3(sb, B1H, B1L, warpM, warpN, lane, acc);

#pragma unroll
    for (int mt = 0; mt < 2; ++mt)
#pragma unroll
        for (int hrow = 0; hrow < 2; ++hrow) {
            int n = n0 + r0 + mt * 16 + hrow * 8;
            if (n < N) {
#pragma unroll
                for (int nidx = 0; nidx < 4; ++nidx) {
                    int c = c0b + nidx * 8;
                    float2 bb = *(const float2*)(b2 + c);
                    *(float2*)(out + (size_t)n * FDIM + c) = make_float2(
                        acc[mt][nidx][hrow * 2 + 0] + bb.x,
                        acc[mt][nidx][hrow * 2 + 1] + bb.y);
                }
            }
        }
}

__global__ void __launch_bounds__(NTH) muproj_mma_kernel(
    const float* __restrict__ mu,
    const __nv_bfloat16* __restrict__ imgT1, const __nv_bfloat16* __restrict__ imgT2,
    const __nv_bfloat16* __restrict__ imgT3,
    float* __restrict__ M1, float* __restrict__ M2, float* __restrict__ M3, int N) {
    extern __shared__ char sm[];
    int tid = threadIdx.x, wid = tid >> 5, lane = tid & 31;
    int warpM = wid >> 2, warpN = wid & 3;
    int n0 = blockIdx.x * TILE;
    uint32_t sb = smem_u32(sm);
    int r0 = warpM * 32 + (lane >> 2);
    int c0b = warpN * 32 + (lane & 3) * 2;

    const __nv_bfloat16* imgs[3] = {imgT1, imgT2, imgT3};
    float* Ms[3] = {M1, M2, M3};

    prefetch_B(sb, B0H, B0L, imgs[0]);
    int it = 0;
    for (int c = 0; c < 3; ++c) {
        __syncthreads();
        for (int i = tid; i < TILE * FDIM; i += NTH) {
            uint32_t r = (uint32_t)(i >> 7), f = (uint32_t)(i & 127);
            float v = 0.f;
            if (n0 + (int)r < N) v = __ldg(mu + ((size_t)(n0 + r) * FDIM + f) * 3 + c);
            unsigned short h, l;
            split1(v, h, l);
            uint32_t off = r * LDSB + f * 2u;
            *(unsigned short*)(sm + AHO + off) = h;
            *(unsigned short*)(sm + ALO + off) = l;
        }
        for (int w = 0; w < 3; ++w, ++it) {
            uint32_t bho = (it & 1) ? B1H : B0H;
            uint32_t blo = (it & 1) ? B1L : B0L;
            cpa_wait<0>();
            __syncthreads();
            if (it < 8)
                prefetch_B(sb, (it & 1) ? B0H : B1H, (it & 1) ? B0L : B1L,
                           imgs[(w + 1) % 3]);
            float acc[2][4][4];
            zero_acc(acc);
            gemm3(sb, bho, blo, warpM, warpN, lane, acc);
            float* dst = Ms[w] + (size_t)c * PLANE;
#pragma unroll
            for (int mt = 0; mt < 2; ++mt)
#pragma unroll
                for (int hrow = 0; hrow < 2; ++hrow) {
                    int n = n0 + r0 + mt * 16 + hrow * 8;
                    if (n < N) {
#pragma unroll
                        for (int nidx = 0; nidx < 4; ++nidx) {
                            int cc = c0b + nidx * 8;
                            *(float2*)(dst + (size_t)n * FDIM + cc) = make_float2(
                                acc[mt][nidx][hrow * 2 + 0], acc[mt][nidx][hrow * 2 + 1]);
                        }
                    }
                }
        }
    }
}

__global__ void __launch_bounds__(NTH) vproj_mma_kernel(
    const float* __restrict__ mv, const __nv_bfloat16* __restrict__ imgV,
    float* __restrict__ out, int N) {
    extern __shared__ char sm[];
    int tid = threadIdx.x, wid = tid >> 5, lane = tid & 31;
    int warpM = wid >> 2, warpN = wid & 3;
    int n0 = blockIdx.x * TILE;
    uint32_t sb = smem_u32(sm);
    int r0 = warpM * 32 + (lane >> 2);
    int c0b = warpN * 32 + (lane & 3) * 2;

    auto prefetch_plane = [&](const float* __restrict__ src) {
        for (int i = tid; i < TILE * 32; i += NTH) {
            uint32_t r = (uint32_t)(i >> 5), q = (uint32_t)(i & 31);
            uint32_t dst = sb + VST + r * 512u + q * 16u;
            if (n0 + (int)r < N) cpa16(dst, src + (size_t)(n0 + r) * FDIM + q * 4);
            else *(uint4*)(sm + VST + r * 512u + q * 16u) = make_uint4(0, 0, 0, 0);
        }
        cpa_commit();
    };

    prefetch_B(sb, VBH, VBL, imgV);
    prefetch_plane(mv);
#pragma unroll 1
    for (int c = 0; c < 3; ++c) {
        cpa_wait<0>();
        __syncthreads();
        for (int i = tid; i < TILE * 16; i += NTH) {
            uint32_t r = (uint32_t)(i >> 4), q = (uint32_t)(i & 15);
            const float* p = (const float*)(sm + VST + r * 512u) + q * 8;
            float4 v0 = *(const float4*)p, v1 = *(const float4*)(p + 4);
            unsigned short h[8], l[8];
            split1(v0.x, h[0], l[0]); split1(v0.y, h[1], l[1]);
            split1(v0.z, h[2], l[2]); split1(v0.w, h[3], l[3]);
            split1(v1.x, h[4], l[4]); split1(v1.y, h[5], l[5]);
            split1(v1.z, h[6], l[6]); split1(v1.w, h[7], l[7]);
            uint32_t off = r * LDSB + q * 16u;
            *(uint4*)(sm + AHO + off) = make_uint4(pack2(h[0], h[1]), pack2(h[2], h[3]),
                                                   pack2(h[4], h[5]), pack2(h[6], h[7]));
            *(uint4*)(sm + ALO + off) = make_uint4(pack2(l[0], l[1]), pack2(l[2], l[3]),
                                                   pack2(l[4], l[5]), pack2(l[6], l[7]));
        }
        __syncthreads();
        if (c < 2) prefetch_plane(mv + (size_t)(c + 1) * PLANE);
        float acc[2][4][4];
        zero_acc(acc);
        gemm3(sb, VBH, VBL, warpM, warpN, lane, acc);
#pragma unroll
        for (int mt = 0; mt < 2; ++mt)
#pragma unroll
            for (int hrow = 0; hrow < 2; ++hrow) {
                int n = n0 + r0 + mt * 16 + hrow * 8;
                if (n < N) {
                    float* o = out + (size_t)n * FDIM * 3 + c;
#pragma unroll
                    for (int nidx = 0; nidx < 4; ++nidx) {
                        int a = c0b + nidx * 8;
                        o[(size_t)a * 3]       = acc[mt][nidx][hrow * 2 + 0];
                        o[(size_t)(a + 1) * 3] = acc[mt][nidx][hrow * 2 + 1];
                    }
                }
            }
    }
}

// ================= combine (DRAM-roofline) =================
__global__ void __launch_bounds__(FDIM) combine_kernel(
    const float* __restrict__ T0, const float* __restrict__ T1,
    const float* __restrict__ T2, const float* __restrict__ T3,
    const float* __restrict__ M0, const float* __restrict__ M1,
    const float* __restrict__ M2, const float* __restrict__ M3,
    float* __restrict__ ms, float* __restrict__ mv, int N) {
    int n = blockIdx.x;
    __shared__ float st[40];
    int tid = threadIdx.x;
    if (tid == 0) st[0] = T0[n];
    if (tid < 3) st[1 + tid] = T1[(size_t)n * 3 + tid];
    if (tid >= 32 && tid < 41) st[4 + tid - 32] = T2[(size_t)n * 9 + (tid - 32)];
    if (tid >= 64 && tid < 91) st[13 + tid - 64] = T3[(size_t)n * 27 + (tid - 64)];
    __syncthreads();

    float t0 = st[0];
    float t1[3], t2[9], t3[27];
#pragma unroll
    for (int k = 0; k < 3; ++k) t1[k] = st[1 + k];
#pragma unroll
    for (int k = 0; k < 9; ++k) t2[k] = st[4 + k];
#pragma unroll
    for (int k = 0; k < 27; ++k) t3[k] = st[13 + k];

    size_t base = (size_t)n * FDIM + tid;
    float m0 = M0[base];
    float m1[3], m2[3], m3[3];
#pragma unroll
    for (int c = 0; c < 3; ++c) {
        m1[c] = M1[base + (size_t)c * PLANE];
        m2[c] = M2[base + (size_t)c * PLANE];
        m3[c] = M3[base + (size_t)c * PLANE];
    }

    float s = t0 * m0;
#pragma unroll
    for (int i = 0; i < 3; ++i) s += m1[i] * t1[i];
#pragma unroll
    for (int i = 0; i < 3; ++i)
#pragma unroll
        for (int j = 0; j < 3; ++j) s += m2[i] * m2[j] * t2[i * 3 + j];
#pragma unroll
    for (int i = 0; i < 3; ++i) {
        float mi = m3[i];
#pragma unroll
        for (int j = 0; j < 3; ++j) {
            float mij = mi * m3[j];
#pragma unroll
            for (int k = 0; k < 3; ++k) s += mij * m3[k] * t3[i * 9 + j * 3 + k];
        }
    }
    ms[base] = s;

#pragma unroll
    for (int i = 0; i < 3; ++i) {
        float v = t1[i] * m0;
#pragma unroll
        for (int j = 0; j < 3; ++j) v += t2[i * 3 + j] * m1[j];
#pragma unroll
        for (int j = 0; j < 3; ++j)
#pragma unroll
            for (int k = 0; k < 3; ++k) v += t3[i * 9 + j * 3 + k] * m2[j] * m2[k];
        mv[base + (size_t)i * PLANE] = v;
    }
}

// ================= launch =================
extern "C" void kernel_launch(void* const* d_in, const int* in_sizes, int n_in,
                              void* d_out, int out_size) {
    const float* feat = (const float*)d_in[0];
    const float* mu   = (const float*)d_in[1];
    const float* T0   = (const float*)d_in[2];
    const float* T1   = (const float*)d_in[3];
    const float* T2   = (const float*)d_in[4];
    const float* T3   = (const float*)d_in[5];
    const float* Wq1  = (const float*)d_in[6];
    const float* bq1  = (const float*)d_in[7];
    const float* Wq2  = (const float*)d_in[8];
    const float* bq2  = (const float*)d_in[9];
    const float* WT1  = (const float*)d_in[10];
    const float* WT2  = (const float*)d_in[11];
    const float* WT3  = (const float*)d_in[12];
    const float* Ws1  = (const float*)d_in[13];
    const float* bs1  = (const float*)d_in[14];
    const float* Ws2  = (const float*)d_in[15];
    const float* bs2  = (const float*)d_in[16];
    const float* Wv   = (const float*)d_in[17];

    int N = in_sizes[0] / FDIM;
    if (N > MAXN) N = MAXN;

    float* out = (float*)d_out;
    float* ms_out = out;
    float* mv_out = out + (size_t)N * FDIM;

    cudaFuncSetAttribute(dense2_mma_kernel, cudaFuncAttributeMaxDynamicSharedMemorySize, (int)SMSZ6);
    cudaFuncSetAttribute(muproj_mma_kernel, cudaFuncAttributeMaxDynamicSharedMemorySize, (int)SMSZ6);
    cudaFuncSetAttribute(vproj_mma_kernel,  cudaFuncAttributeMaxDynamicSharedMemorySize, (int)SMSZV);

    float *pM0, *pM1, *pM2, *pM3, *pms, *pmv;
    __nv_bfloat16* pW;
    cudaGetSymbolAddress((void**)&pM0, g_M0);
    cudaGetSymbolAddress((void**)&pM1, g_M1);
    cudaGetSymbolAddress((void**)&pM2, g_M2);
    cudaGetSymbolAddress((void**)&pM3, g_M3);
    cudaGetSymbolAddress((void**)&pms, g_ms);
    cudaGetSymbolAddress((void**)&pmv, g_mv);
    cudaGetSymbolAddress((void**)&pW,  g_Wimg);

    WPtrs wp;
    wp.p[0] = Wq1; wp.p[1] = Wq2; wp.p[2] = WT1; wp.p[3] = WT2;
    wp.p[4] = WT3; wp.p[5] = Ws1; wp.p[6] = Ws2; wp.p[7] = Wv;
    prep_weights<<<8, 256>>>(wp);

    int nb = (N + TILE - 1) / TILE;
    dense2_mma_kernel<<<nb, NTH, SMSZ6>>>(feat, pW + 0 * 32768, bq1, pW + 1 * 32768, bq2, pM0, N);
    muproj_mma_kernel<<<nb, NTH, SMSZ6>>>(mu, pW + 2 * 32768, pW + 3 * 32768, pW + 4 * 32768,
                                          pM1, pM2, pM3, N);
    combine_kernel<<<N, FDIM>>>(T0, T1, T2, T3, pM0, pM1, pM2, pM3, pms, pmv, N);
    dense2_mma_kernel<<<nb, NTH, SMSZ6>>>(pms, pW + 5 * 32768, bs1, pW + 6 * 32768, bs2, ms_out, N);
    vproj_mma_kernel<<<nb, NTH, SMSZV>>>(pmv, pW + 7 * 32768, mv_out, N);
}

// round 10
// speedup vs baseline: 1.3052x; 1.3052x over previous
#include <cuda_runtime.h>
#include <cuda_bf16.h>
#include <cstdint>
#include <math.h>

#define MAXN 50000
#define FDIM 128
#define TILE 128
#define NTH  256
#define PLANE ((size_t)MAXN * FDIM)

// padded bf16 planes: row stride 136 bf16 = 272 B (ldmatrix conflict-free)
#define LDSB 272u
#define PLB  34816u
#define AHO 0u
#define ALO PLB
#define B0H (2u*PLB)
#define B0L (3u*PLB)
#define B1H (4u*PLB)
#define B1L (5u*PLB)
#define SMSZ6 (6u*PLB)            // 208896
#define VBH (2u*PLB)
#define VBL (3u*PLB)
#define VST (4u*PLB)

// -------- scratch --------
__device__ float g_M0[MAXN * FDIM];
__device__ float g_M1[3][MAXN * FDIM];
__device__ float g_M2[3][MAXN * FDIM];
__device__ float g_M3[3][MAXN * FDIM];
__device__ float g_ms[MAXN * FDIM];
__device__ float g_mv[3][MAXN * FDIM];
__device__ __nv_bfloat16 g_Wimg[8][32768];   // [hi 16384 | lo 16384], [out][in]

// ================= helpers =================
__device__ __forceinline__ uint32_t smem_u32(const void* p) {
    uint32_t a;
    asm("{ .reg .u64 t; cvta.to.shared.u64 t, %1; cvt.u32.u64 %0, t; }" : "=r"(a) : "l"(p));
    return a;
}
__device__ __forceinline__ void cpa16(uint32_t dst, const void* src) {
    asm volatile("cp.async.cg.shared.global [%0], [%1], 16;" :: "r"(dst), "l"(src));
}
__device__ __forceinline__ void cpa_commit() { asm volatile("cp.async.commit_group;"); }
template <int K> __device__ __forceinline__ void cpa_wait() {
    asm volatile("cp.async.wait_group %0;" :: "n"(K));
}
__device__ __forceinline__ void ldm4(uint32_t* r, uint32_t addr) {
    asm volatile("ldmatrix.sync.aligned.m8n8.x4.shared.b16 {%0,%1,%2,%3}, [%4];"
                 : "=r"(r[0]), "=r"(r[1]), "=r"(r[2]), "=r"(r[3]) : "r"(addr));
}
__device__ __forceinline__ void mma16816(float* c, const uint32_t* a, uint32_t b0, uint32_t b1) {
    asm volatile(
        "mma.sync.aligned.m16n8k16.row.col.f32.bf16.bf16.f32 "
        "{%0,%1,%2,%3}, {%4,%5,%6,%7}, {%8,%9}, {%0,%1,%2,%3};"
        : "+f"(c[0]), "+f"(c[1]), "+f"(c[2]), "+f"(c[3])
        : "r"(a[0]), "r"(a[1]), "r"(a[2]), "r"(a[3]), "r"(b0), "r"(b1));
}
__device__ __forceinline__ void split1(float x, unsigned short& h, unsigned short& l) {
    __nv_bfloat16 hb = __float2bfloat16(x);
    float r = x - __bfloat162float(hb);
    __nv_bfloat16 lb = __float2bfloat16(r);
    h = *(unsigned short*)&hb;
    l = *(unsigned short*)&lb;
}
__device__ __forceinline__ uint32_t pack2(unsigned short a, unsigned short b) {
    return (uint32_t)a | ((uint32_t)b << 16);
}
__device__ __forceinline__ float sigf(float x) { return 1.f / (1.f + __expf(-x)); }

__device__ __forceinline__ void prefetch_B(uint32_t sb, uint32_t bho, uint32_t blo,
                                           const __nv_bfloat16* __restrict__ img) {
    for (int i = threadIdx.x; i < 4096; i += NTH) {
        int half = i >> 11, idx = i & 2047;
        uint32_t r = (uint32_t)(idx >> 4), q = (uint32_t)(idx & 15);
        uint32_t dst = sb + (half ? blo : bho) + r * LDSB + q * 16u;
        cpa16(dst, (const uint4*)(img + half * 16384) + idx);
    }
    cpa_commit();
}

__device__ __forceinline__ void load_split_A(char* sm, const float* __restrict__ src,
                                             int n0, int N) {
    for (int i = threadIdx.x; i < TILE * 16; i += NTH) {
        uint32_t r = (uint32_t)(i >> 4), q = (uint32_t)(i & 15);
        float4 v0 = make_float4(0.f, 0.f, 0.f, 0.f), v1 = v0;
        if (n0 + (int)r < N) {
            const float* p = src + (size_t)(n0 + r) * FDIM + q * 8;
            v0 = *(const float4*)p;
            v1 = *(const float4*)(p + 4);
        }
        unsigned short h[8], l[8];
        split1(v0.x, h[0], l[0]); split1(v0.y, h[1], l[1]);
        split1(v0.z, h[2], l[2]); split1(v0.w, h[3], l[3]);
        split1(v1.x, h[4], l[4]); split1(v1.y, h[5], l[5]);
        split1(v1.z, h[6], l[6]); split1(v1.w, h[7], l[7]);
        uint32_t off = r * LDSB + q * 16u;
        *(uint4*)(sm + AHO + off) = make_uint4(pack2(h[0], h[1]), pack2(h[2], h[3]),
                                               pack2(h[4], h[5]), pack2(h[6], h[7]));
        *(uint4*)(sm + ALO + off) = make_uint4(pack2(l[0], l[1]), pack2(l[2], l[3]),
                                               pack2(l[4], l[5]), pack2(l[6], l[7]));
    }
}

// ---- 3-term split GEMM (R8-proven): 8 warps, grid 4(M)x2(N), warp tile 32x64 ----
__device__ __forceinline__ void gemm3(uint32_t sb, uint32_t bho, uint32_t blo,
                                      int warpM, int warpN, int lane, float acc[2][8][4]) {
    uint32_t rowA = (uint32_t)(warpM * 32 + (lane & 15)) * LDSB;
    uint32_t rowB = (uint32_t)(warpN * 64 + (lane & 15)) * LDSB;
    uint32_t kh = (uint32_t)((lane >> 4) * 8) * 2u;
#pragma unroll
    for (int kc = 0; kc < 8; ++kc) {
        uint32_t kof = kh + (uint32_t)kc * 32u;
        uint32_t ah[2][4], al[2][4], bh[4][4], bl[4][4];
#pragma unroll
        for (int mt = 0; mt < 2; ++mt) {
            uint32_t a = rowA + (uint32_t)(mt * 16) * LDSB + kof;
            ldm4(ah[mt], sb + AHO + a);
            ldm4(al[mt], sb + ALO + a);
        }
#pragma unroll
        for (int nt = 0; nt < 4; ++nt) {
            uint32_t b = rowB + (uint32_t)(nt * 16) * LDSB + kof;
            ldm4(bh[nt], sb + bho + b);
            ldm4(bl[nt], sb + blo + b);
        }
#pragma unroll
        for (int mt = 0; mt < 2; ++mt)
#pragma unroll
            for (int nt = 0; nt < 4; ++nt) {
                mma16816(acc[mt][nt * 2 + 0], ah[mt], bh[nt][0], bh[nt][2]);
                mma16816(acc[mt][nt * 2 + 1], ah[mt], bh[nt][1], bh[nt][3]);
                mma16816(acc[mt][nt * 2 + 0], ah[mt], bl[nt][0], bl[nt][2]);
                mma16816(acc[mt][nt * 2 + 1], ah[mt], bl[nt][1], bl[nt][3]);
                mma16816(acc[mt][nt * 2 + 0], al[mt], bh[nt][0], bh[nt][2]);
                mma16816(acc[mt][nt * 2 + 1], al[mt], bh[nt][1], bh[nt][3]);
            }
    }
}
__device__ __forceinline__ void zero_acc(float acc[2][8][4]) {
#pragma unroll
    for (int m = 0; m < 2; ++m)
#pragma unroll
        for (int n = 0; n < 8; ++n)
#pragma unroll
            for (int j = 0; j < 4; ++j) acc[m][n][j] = 0.f;
}

// ================= device bodies =================
__device__ void dense2_body(char* sm, const float* __restrict__ in,
                            const __nv_bfloat16* __restrict__ img1, const float* __restrict__ b1,
                            const __nv_bfloat16* __restrict__ img2, const float* __restrict__ b2,
                            float* __restrict__ out, int tileIdx, int N) {
    int tid = threadIdx.x, wid = tid >> 5, lane = tid & 31;
    int warpM = wid >> 1, warpN = wid & 1;
    int n0 = tileIdx * TILE;
    uint32_t sb = smem_u32(sm);
    int r0 = warpM * 32 + (lane >> 2);
    int c0b = warpN * 64 + (lane & 3) * 2;

    prefetch_B(sb, B0H, B0L, img1);
    prefetch_B(sb, B1H, B1L, img2);
    load_split_A(sm, in, n0, N);
    cpa_wait<1>();
    __syncthreads();

    float acc[2][8][4];
    zero_acc(acc);
    gemm3(sb, B0H, B0L, warpM, warpN, lane, acc);
    __syncthreads();

#pragma unroll
    for (int mt = 0; mt < 2; ++mt)
#pragma unroll
        for (int nidx = 0; nidx < 8; ++nidx) {
            int c = c0b + nidx * 8;
            float2 bb = *(const float2*)(b1 + c);
#pragma unroll
            for (int hrow = 0; hrow < 2; ++hrow) {
                uint32_t r = (uint32_t)(r0 + mt * 16 + hrow * 8);
                float x = acc[mt][nidx][hrow * 2 + 0] + bb.x;
                float y = acc[mt][nidx][hrow * 2 + 1] + bb.y;
                x *= sigf(x); y *= sigf(y);
                unsigned short hx, lx, hy, ly;
                split1(x, hx, lx); split1(y, hy, ly);
                uint32_t off = r * LDSB + (uint32_t)c * 2u;
                *(uint32_t*)(sm + AHO + off) = pack2(hx, hy);
                *(uint32_t*)(sm + ALO + off) = pack2(lx, ly);
            }
        }
    cpa_wait<0>();
    __syncthreads();

    zero_acc(acc);
    gemm3(sb, B1H, B1L, warpM, warpN, lane, acc);

#pragma unroll
    for (int mt = 0; mt < 2; ++mt)
#pragma unroll
        for (int hrow = 0; hrow < 2; ++hrow) {
            int n = n0 + r0 + mt * 16 + hrow * 8;
            if (n < N) {
#pragma unroll
                for (int nidx = 0; nidx < 8; ++nidx) {
                    int c = c0b + nidx * 8;
                    float2 bb = *(const float2*)(b2 + c);
                    *(float2*)(out + (size_t)n * FDIM + c) = make_float2(
                        acc[mt][nidx][hrow * 2 + 0] + bb.x,
                        acc[mt][nidx][hrow * 2 + 1] + bb.y);
                }
            }
        }
}

__device__ void muproj_body(char* sm, const float* __restrict__ mu,
                            const __nv_bfloat16* __restrict__ imgT1,
                            const __nv_bfloat16* __restrict__ imgT2,
                            const __nv_bfloat16* __restrict__ imgT3,
                            float* __restrict__ M1, float* __restrict__ M2,
                            float* __restrict__ M3, int tileIdx, int N) {
    int tid = threadIdx.x, wid = tid >> 5, lane = tid & 31;
    int warpM = wid >> 1, warpN = wid & 1;
    int n0 = tileIdx * TILE;
    uint32_t sb = smem_u32(sm);
    int r0 = warpM * 32 + (lane >> 2);
    int c0b = warpN * 64 + (lane & 3) * 2;

    const __nv_bfloat16* imgs[3] = {imgT1, imgT2, imgT3};
    float* Ms[3] = {M1, M2, M3};

    prefetch_B(sb, B0H, B0L, imgs[0]);
    int it = 0;
    for (int c = 0; c < 3; ++c) {
        __syncthreads();
        for (int i = tid; i < TILE * FDIM; i += NTH) {
            uint32_t r = (uint32_t)(i >> 7), f = (uint32_t)(i & 127);
            float v = 0.f;
            if (n0 + (int)r < N) v = __ldg(mu + ((size_t)(n0 + r) * FDIM + f) * 3 + c);
            unsigned short h, l;
            split1(v, h, l);
            uint32_t off = r * LDSB + f * 2u;
            *(unsigned short*)(sm + AHO + off) = h;
            *(unsigned short*)(sm + ALO + off) = l;
        }
        for (int w = 0; w < 3; ++w, ++it) {
            uint32_t bho = (it & 1) ? B1H : B0H;
            uint32_t blo = (it & 1) ? B1L : B0L;
            cpa_wait<0>();
            __syncthreads();
            if (it < 8)
                prefetch_B(sb, (it & 1) ? B0H : B1H, (it & 1) ? B0L : B1L,
                           imgs[(w + 1) % 3]);
            float acc[2][8][4];
            zero_acc(acc);
            gemm3(sb, bho, blo, warpM, warpN, lane, acc);
            float* dst = Ms[w] + (size_t)c * PLANE;
#pragma unroll
            for (int mt = 0; mt < 2; ++mt)
#pragma unroll
                for (int hrow = 0; hrow < 2; ++hrow) {
                    int n = n0 + r0 + mt * 16 + hrow * 8;
                    if (n < N) {
#pragma unroll
                        for (int nidx = 0; nidx < 8; ++nidx) {
                            int cc = c0b + nidx * 8;
                            *(float2*)(dst + (size_t)n * FDIM + cc) = make_float2(
                                acc[mt][nidx][hrow * 2 + 0], acc[mt][nidx][hrow * 2 + 1]);
                        }
                    }
                }
        }
    }
}

__device__ void vproj_body(char* sm, const float* __restrict__ mv,
                           const __nv_bfloat16* __restrict__ imgV,
                           float* __restrict__ out, int tileIdx, int N) {
    int tid = threadIdx.x, wid = tid >> 5, lane = tid & 31;
    int warpM = wid >> 1, warpN = wid & 1;
    int n0 = tileIdx * TILE;
    uint32_t sb = smem_u32(sm);
    int r0 = warpM * 32 + (lane >> 2);
    int c0b = warpN * 64 + (lane & 3) * 2;

    auto prefetch_plane = [&](const float* __restrict__ src) {
        for (int i = tid; i < TILE * 32; i += NTH) {
            uint32_t r = (uint32_t)(i >> 5), q = (uint32_t)(i & 31);
            uint32_t dst = sb + VST + r * 512u + q * 16u;
            if (n0 + (int)r < N) cpa16(dst, src + (size_t)(n0 + r) * FDIM + q * 4);
            else *(uint4*)(sm + VST + r * 512u + q * 16u) = make_uint4(0, 0, 0, 0);
        }
        cpa_commit();
    };

    prefetch_B(sb, VBH, VBL, imgV);
    prefetch_plane(mv);
#pragma unroll 1
    for (int c = 0; c < 3; ++c) {
        cpa_wait<0>();
        __syncthreads();
        for (int i = tid; i < TILE * 16; i += NTH) {
            uint32_t r = (uint32_t)(i >> 4), q = (uint32_t)(i & 15);
            const float* p = (const float*)(sm + VST + r * 512u) + q * 8;
            float4 v0 = *(const float4*)p, v1 = *(const float4*)(p + 4);
            unsigned short h[8], l[8];
            split1(v0.x, h[0], l[0]); split1(v0.y, h[1], l[1]);
            split1(v0.z, h[2], l[2]); split1(v0.w, h[3], l[3]);
            split1(v1.x, h[4], l[4]); split1(v1.y, h[5], l[5]);
            split1(v1.z, h[6], l[6]); split1(v1.w, h[7], l[7]);
            uint32_t off = r * LDSB + q * 16u;
            *(uint4*)(sm + AHO + off) = make_uint4(pack2(h[0], h[1]), pack2(h[2], h[3]),
                                                   pack2(h[4], h[5]), pack2(h[6], h[7]));
            *(uint4*)(sm + ALO + off) = make_uint4(pack2(l[0], l[1]), pack2(l[2], l[3]),
                                                   pack2(l[4], l[5]), pack2(l[6], l[7]));
        }
        __syncthreads();
        if (c < 2) prefetch_plane(mv + (size_t)(c + 1) * PLANE);
        float acc[2][8][4];
        zero_acc(acc);
        gemm3(sb, VBH, VBL, warpM, warpN, lane, acc);
#pragma unroll
        for (int mt = 0; mt < 2; ++mt)
#pragma unroll
            for (int hrow = 0; hrow < 2; ++hrow) {
                int n = n0 + r0 + mt * 16 + hrow * 8;
                if (n < N) {
                    float* o = out + (size_t)n * FDIM * 3 + c;
#pragma unroll
                    for (int nidx = 0; nidx < 8; ++nidx) {
                        int a = c0b + nidx * 8;
                        o[(size_t)a * 3]       = acc[mt][nidx][hrow * 2 + 0];
                        o[(size_t)(a + 1) * 3] = acc[mt][nidx][hrow * 2 + 1];
                    }
                }
            }
    }
}

// ================= merged kernels =================
// phase 1: even blocks -> dense2(feat), odd blocks -> muproj(mu)
__global__ void __launch_bounds__(NTH) phase1_kernel(
    const float* __restrict__ feat, const float* __restrict__ mu,
    const __nv_bfloat16* __restrict__ imgQ1, const float* __restrict__ bq1,
    const __nv_bfloat16* __restrict__ imgQ2, const float* __restrict__ bq2,
    const __nv_bfloat16* __restrict__ imgT1, const __nv_bfloat16* __restrict__ imgT2,
    const __nv_bfloat16* __restrict__ imgT3,
    float* __restrict__ M0, float* __restrict__ M1, float* __restrict__ M2,
    float* __restrict__ M3, int N) {
    extern __shared__ char sm[];
    int b = blockIdx.x;
    if (b & 1) muproj_body(sm, mu, imgT1, imgT2, imgT3, M1, M2, M3, b >> 1, N);
    else       dense2_body(sm, feat, imgQ1, bq1, imgQ2, bq2, M0, b >> 1, N);
}

// phase 2: even blocks -> dense2(ms), odd blocks -> vproj(mv)
__global__ void __launch_bounds__(NTH) phase2_kernel(
    const float* __restrict__ ms, const float* __restrict__ mv,
    const __nv_bfloat16* __restrict__ imgS1, const float* __restrict__ bs1,
    const __nv_bfloat16* __restrict__ imgS2, const float* __restrict__ bs2,
    const __nv_bfloat16* __restrict__ imgV,
    float* __restrict__ ms_out, float* __restrict__ mv_out, int N) {
    extern __shared__ char sm[];
    int b = blockIdx.x;
    if (b & 1) vproj_body(sm, mv, imgV, mv_out, b >> 1, N);
    else       dense2_body(sm, ms, imgS1, bs1, imgS2, bs2, ms_out, b >> 1, N);
}

// ================= prep =================
struct WPtrs { const float* p[8]; };
__global__ void prep_weights(WPtrs wp) {
    int w = blockIdx.x;
    const float* src = wp.p[w];
    __nv_bfloat16* hi = g_Wimg[w];
    __nv_bfloat16* lo = g_Wimg[w] + 16384;
    for (int i = threadIdx.x; i < 16384; i += blockDim.x) {
        int k = i >> 7, g = i & 127;
        unsigned short h, l;
        split1(src[i], h, l);
        hi[g * 128 + k] = *(__nv_bfloat16*)&h;
        lo[g * 128 + k] = *(__nv_bfloat16*)&l;
    }
}

// ================= combine (DRAM-roofline) =================
__global__ void __launch_bounds__(FDIM) combine_kernel(
    const float* __restrict__ T0, const float* __restrict__ T1,
    const float* __restrict__ T2, const float* __restrict__ T3,
    const float* __restrict__ M0, const float* __restrict__ M1,
    const float* __restrict__ M2, const float* __restrict__ M3,
    float* __restrict__ ms, float* __restrict__ mv, int N) {
    int n = blockIdx.x;
    __shared__ float st[40];
    int tid = threadIdx.x;
    if (tid == 0) st[0] = T0[n];
    if (tid < 3) st[1 + tid] = T1[(size_t)n * 3 + tid];
    if (tid >= 32 && tid < 41) st[4 + tid - 32] = T2[(size_t)n * 9 + (tid - 32)];
    if (tid >= 64 && tid < 91) st[13 + tid - 64] = T3[(size_t)n * 27 + (tid - 64)];
    __syncthreads();

    float t0 = st[0];
    float t1[3], t2[9], t3[27];
#pragma unroll
    for (int k = 0; k < 3; ++k) t1[k] = st[1 + k];
#pragma unroll
    for (int k = 0; k < 9; ++k) t2[k] = st[4 + k];
#pragma unroll
    for (int k = 0; k < 27; ++k) t3[k] = st[13 + k];

    size_t base = (size_t)n * FDIM + tid;
    float m0 = M0[base];
    float m1[3], m2[3], m3[3];
#pragma unroll
    for (int c = 0; c < 3; ++c) {
        m1[c] = M1[base + (size_t)c * PLANE];
        m2[c] = M2[base + (size_t)c * PLANE];
        m3[c] = M3[base + (size_t)c * PLANE];
    }

    float s = t0 * m0;
#pragma unroll
    for (int i = 0; i < 3; ++i) s += m1[i] * t1[i];
#pragma unroll
    for (int i = 0; i < 3; ++i)
#pragma unroll
        for (int j = 0; j < 3; ++j) s += m2[i] * m2[j] * t2[i * 3 + j];
#pragma unroll
    for (int i = 0; i < 3; ++i) {
        float mi = m3[i];
#pragma unroll
        for (int j = 0; j < 3; ++j) {
            float mij = mi * m3[j];
#pragma unroll
            for (int k = 0; k < 3; ++k) s += mij * m3[k] * t3[i * 9 + j * 3 + k];
        }
    }
    ms[base] = s;

#pragma unroll
    for (int i = 0; i < 3; ++i) {
        float v = t1[i] * m0;
#pragma unroll
        for (int j = 0; j < 3; ++j) v += t2[i * 3 + j] * m1[j];
#pragma unroll
        for (int j = 0; j < 3; ++j)
#pragma unroll
            for (int k = 0; k < 3; ++k) v += t3[i * 9 + j * 3 + k] * m2[j] * m2[k];
        mv[base + (size_t)i * PLANE] = v;
    }
}

// ================= launch =================
extern "C" void kernel_launch(void* const* d_in, const int* in_sizes, int n_in,
                              void* d_out, int out_size) {
    const float* feat = (const float*)d_in[0];
    const float* mu   = (const float*)d_in[1];
    const float* T0   = (const float*)d_in[2];
    const float* T1   = (const float*)d_in[3];
    const float* T2   = (const float*)d_in[4];
    const float* T3   = (const float*)d_in[5];
    const float* Wq1  = (const float*)d_in[6];
    const float* bq1  = (const float*)d_in[7];
    const float* Wq2  = (const float*)d_in[8];
    const float* bq2  = (const float*)d_in[9];
    const float* WT1  = (const float*)d_in[10];
    const float* WT2  = (const float*)d_in[11];
    const float* WT3  = (const float*)d_in[12];
    const float* Ws1  = (const float*)d_in[13];
    const float* bs1  = (const float*)d_in[14];
    const float* Ws2  = (const float*)d_in[15];
    const float* bs2  = (const float*)d_in[16];
    const float* Wv   = (const float*)d_in[17];

    int N = in_sizes[0] / FDIM;
    if (N > MAXN) N = MAXN;

    float* out = (float*)d_out;
    float* ms_out = out;
    float* mv_out = out + (size_t)N * FDIM;

    cudaFuncSetAttribute(phase1_kernel, cudaFuncAttributeMaxDynamicSharedMemorySize, (int)SMSZ6);
    cudaFuncSetAttribute(phase2_kernel, cudaFuncAttributeMaxDynamicSharedMemorySize, (int)SMSZ6);

    float *pM0, *pM1, *pM2, *pM3, *pms, *pmv;
    __nv_bfloat16* pW;
    cudaGetSymbolAddress((void**)&pM0, g_M0);
    cudaGetSymbolAddress((void**)&pM1, g_M1);
    cudaGetSymbolAddress((void**)&pM2, g_M2);
    cudaGetSymbolAddress((void**)&pM3, g_M3);
    cudaGetSymbolAddress((void**)&pms, g_ms);
    cudaGetSymbolAddress((void**)&pmv, g_mv);
    cudaGetSymbolAddress((void**)&pW,  g_Wimg);

    WPtrs wp;
    wp.p[0] = Wq1; wp.p[1] = Wq2; wp.p[2] = WT1; wp.p[3] = WT2;
    wp.p[4] = WT3; wp.p[5] = Ws1; wp.p[6] = Ws2; wp.p[7] = Wv;
    prep_weights<<<8, 256>>>(wp);

    int nb = (N + TILE - 1) / TILE;
    phase1_kernel<<<2 * nb, NTH, SMSZ6>>>(feat, mu,
                                          pW + 0 * 32768, bq1, pW + 1 * 32768, bq2,
                                          pW + 2 * 32768, pW + 3 * 32768, pW + 4 * 32768,
                                          pM0, pM1, pM2, pM3, N);
    combine_kernel<<<N, FDIM>>>(T0, T1, T2, T3, pM0, pM1, pM2, pM3, pms, pmv, N);
    phase2_kernel<<<2 * nb, NTH, SMSZ6>>>(pms, pmv,
                                          pW + 5 * 32768, bs1, pW + 6 * 32768, bs2,
                                          pW + 7 * 32768, ms_out, mv_out, N);
}

// round 11
// speedup vs baseline: 1.3057x; 1.0004x over previous
#include <cuda_runtime.h>
#include <cuda_bf16.h>
#include <cstdint>
#include <math.h>

#define MAXN 50000
#define FDIM 128
#define TILE 128
#define NTH  256
#define PLANE ((size_t)MAXN * FDIM)

// padded bf16 planes: row stride 136 bf16 = 272 B (ldmatrix conflict-free)
#define LDSB 272u
#define PLB  34816u
#define AHO 0u
#define ALO PLB
#define B0H (2u*PLB)
#define B0L (3u*PLB)
#define B1H (4u*PLB)
#define B1L (5u*PLB)
#define SMSZ6 (6u*PLB)            // 208896
#define VBH (2u*PLB)
#define VBL (3u*PLB)
#define VST (4u*PLB)

// -------- scratch --------
__device__ float g_M0[MAXN * FDIM];
__device__ float g_M1[3][MAXN * FDIM];
__device__ float g_M2[3][MAXN * FDIM];
__device__ float g_M3[3][MAXN * FDIM];
__device__ float g_ms[MAXN * FDIM];
__device__ float g_mv[3][MAXN * FDIM];
__device__ __nv_bfloat16 g_Wimg[8][32768];   // [hi 16384 | lo 16384], [out][in]

// ================= helpers =================
__device__ __forceinline__ uint32_t smem_u32(const void* p) {
    uint32_t a;
    asm("{ .reg .u64 t; cvta.to.shared.u64 t, %1; cvt.u32.u64 %0, t; }" : "=r"(a) : "l"(p));
    return a;
}
__device__ __forceinline__ void cpa16(uint32_t dst, const void* src) {
    asm volatile("cp.async.cg.shared.global [%0], [%1], 16;" :: "r"(dst), "l"(src));
}
__device__ __forceinline__ void cpa_commit() { asm volatile("cp.async.commit_group;"); }
template <int K> __device__ __forceinline__ void cpa_wait() {
    asm volatile("cp.async.wait_group %0;" :: "n"(K));
}
__device__ __forceinline__ void ldm4(uint32_t* r, uint32_t addr) {
    asm volatile("ldmatrix.sync.aligned.m8n8.x4.shared.b16 {%0,%1,%2,%3}, [%4];"
                 : "=r"(r[0]), "=r"(r[1]), "=r"(r[2]), "=r"(r[3]) : "r"(addr));
}
__device__ __forceinline__ void mma16816(float* c, const uint32_t* a, uint32_t b0, uint32_t b1) {
    asm volatile(
        "mma.sync.aligned.m16n8k16.row.col.f32.bf16.bf16.f32 "
        "{%0,%1,%2,%3}, {%4,%5,%6,%7}, {%8,%9}, {%0,%1,%2,%3};"
        : "+f"(c[0]), "+f"(c[1]), "+f"(c[2]), "+f"(c[3])
        : "r"(a[0]), "r"(a[1]), "r"(a[2]), "r"(a[3]), "r"(b0), "r"(b1));
}
__device__ __forceinline__ void split1(float x, unsigned short& h, unsigned short& l) {
    __nv_bfloat16 hb = __float2bfloat16(x);
    float r = x - __bfloat162float(hb);
    __nv_bfloat16 lb = __float2bfloat16(r);
    h = *(unsigned short*)&hb;
    l = *(unsigned short*)&lb;
}
__device__ __forceinline__ uint32_t pack2(unsigned short a, unsigned short b) {
    return (uint32_t)a | ((uint32_t)b << 16);
}
__device__ __forceinline__ float sigf(float x) { return 1.f / (1.f + __expf(-x)); }

__device__ __forceinline__ void prefetch_B(uint32_t sb, uint32_t bho, uint32_t blo,
                                           const __nv_bfloat16* __restrict__ img) {
    for (int i = threadIdx.x; i < 4096; i += NTH) {
        int half = i >> 11, idx = i & 2047;
        uint32_t r = (uint32_t)(idx >> 4), q = (uint32_t)(idx & 15);
        uint32_t dst = sb + (half ? blo : bho) + r * LDSB + q * 16u;
        cpa16(dst, (const uint4*)(img + half * 16384) + idx);
    }
    cpa_commit();
}

__device__ __forceinline__ void load_split_A(char* sm, const float* __restrict__ src,
                                             int n0, int N) {
    for (int i = threadIdx.x; i < TILE * 16; i += NTH) {
        uint32_t r = (uint32_t)(i >> 4), q = (uint32_t)(i & 15);
        float4 v0 = make_float4(0.f, 0.f, 0.f, 0.f), v1 = v0;
        if (n0 + (int)r < N) {
            const float* p = src + (size_t)(n0 + r) * FDIM + q * 8;
            v0 = *(const float4*)p;
            v1 = *(const float4*)(p + 4);
        }
        unsigned short h[8], l[8];
        split1(v0.x, h[0], l[0]); split1(v0.y, h[1], l[1]);
        split1(v0.z, h[2], l[2]); split1(v0.w, h[3], l[3]);
        split1(v1.x, h[4], l[4]); split1(v1.y, h[5], l[5]);
        split1(v1.z, h[6], l[6]); split1(v1.w, h[7], l[7]);
        uint32_t off = r * LDSB + q * 16u;
        *(uint4*)(sm + AHO + off) = make_uint4(pack2(h[0], h[1]), pack2(h[2], h[3]),
                                               pack2(h[4], h[5]), pack2(h[6], h[7]));
        *(uint4*)(sm + ALO + off) = make_uint4(pack2(l[0], l[1]), pack2(l[2], l[3]),
                                               pack2(l[4], l[5]), pack2(l[6], l[7]));
    }
}

// ---- 3-term split GEMM, software-pipelined fragment loads ----
// 8 warps: grid 4(M)x2(N), warp tile 32x64; acc[mt2][nidx8][4]
struct Frags { uint32_t ah[2][4], al[2][4], bh[4][4], bl[4][4]; };

__device__ __forceinline__ void load_frags(Frags& f, uint32_t sb, uint32_t bho, uint32_t blo,
                                           uint32_t rowA, uint32_t rowB, uint32_t kof) {
#pragma unroll
    for (int mt = 0; mt < 2; ++mt) {
        uint32_t a = rowA + (uint32_t)(mt * 16) * LDSB + kof;
        ldm4(f.ah[mt], sb + AHO + a);
        ldm4(f.al[mt], sb + ALO + a);
    }
#pragma unroll
    for (int nt = 0; nt < 4; ++nt) {
        uint32_t b = rowB + (uint32_t)(nt * 16) * LDSB + kof;
        ldm4(f.bh[nt], sb + bho + b);
        ldm4(f.bl[nt], sb + blo + b);
    }
}
__device__ __forceinline__ void mma_frags(float acc[2][8][4], const Frags& f) {
#pragma unroll
    for (int mt = 0; mt < 2; ++mt)
#pragma unroll
        for (int nt = 0; nt < 4; ++nt) {
            mma16816(acc[mt][nt * 2 + 0], f.ah[mt], f.bh[nt][0], f.bh[nt][2]);
            mma16816(acc[mt][nt * 2 + 1], f.ah[mt], f.bh[nt][1], f.bh[nt][3]);
            mma16816(acc[mt][nt * 2 + 0], f.ah[mt], f.bl[nt][0], f.bl[nt][2]);
            mma16816(acc[mt][nt * 2 + 1], f.ah[mt], f.bl[nt][1], f.bl[nt][3]);
            mma16816(acc[mt][nt * 2 + 0], f.al[mt], f.bh[nt][0], f.bh[nt][2]);
            mma16816(acc[mt][nt * 2 + 1], f.al[mt], f.bh[nt][1], f.bh[nt][3]);
        }
}

__device__ __forceinline__ void gemm3(uint32_t sb, uint32_t bho, uint32_t blo,
                                      int warpM, int warpN, int lane, float acc[2][8][4]) {
    uint32_t rowA = (uint32_t)(warpM * 32 + (lane & 15)) * LDSB;
    uint32_t rowB = (uint32_t)(warpN * 64 + (lane & 15)) * LDSB;
    uint32_t kh = (uint32_t)((lane >> 4) * 8) * 2u;
    Frags f0, f1;
    load_frags(f0, sb, bho, blo, rowA, rowB, kh);
#pragma unroll
    for (int kc = 0; kc < 8; ++kc) {
        Frags& cur = (kc & 1) ? f1 : f0;
        Frags& nxt = (kc & 1) ? f0 : f1;
        if (kc < 7)
            load_frags(nxt, sb, bho, blo, rowA, rowB, kh + (uint32_t)(kc + 1) * 32u);
        mma_frags(acc, cur);
    }
}
__device__ __forceinline__ void zero_acc(float acc[2][8][4]) {
#pragma unroll
    for (int m = 0; m < 2; ++m)
#pragma unroll
        for (int n = 0; n < 8; ++n)
#pragma unroll
            for (int j = 0; j < 4; ++j) acc[m][n][j] = 0.f;
}

// ================= device bodies =================
__device__ void dense2_body(char* sm, const float* __restrict__ in,
                            const __nv_bfloat16* __restrict__ img1, const float* __restrict__ b1,
                            const __nv_bfloat16* __restrict__ img2, const float* __restrict__ b2,
                            float* __restrict__ out, int tileIdx, int N) {
    int tid = threadIdx.x, wid = tid >> 5, lane = tid & 31;
    int warpM = wid >> 1, warpN = wid & 1;
    int n0 = tileIdx * TILE;
    uint32_t sb = smem_u32(sm);
    int r0 = warpM * 32 + (lane >> 2);
    int c0b = warpN * 64 + (lane & 3) * 2;

    prefetch_B(sb, B0H, B0L, img1);
    prefetch_B(sb, B1H, B1L, img2);
    load_split_A(sm, in, n0, N);
    cpa_wait<1>();
    __syncthreads();

    float acc[2][8][4];
    zero_acc(acc);
    gemm3(sb, B0H, B0L, warpM, warpN, lane, acc);
    __syncthreads();

#pragma unroll
    for (int mt = 0; mt < 2; ++mt)
#pragma unroll
        for (int nidx = 0; nidx < 8; ++nidx) {
            int c = c0b + nidx * 8;
            float2 bb = *(const float2*)(b1 + c);
#pragma unroll
            for (int hrow = 0; hrow < 2; ++hrow) {
                uint32_t r = (uint32_t)(r0 + mt * 16 + hrow * 8);
                float x = acc[mt][nidx][hrow * 2 + 0] + bb.x;
                float y = acc[mt][nidx][hrow * 2 + 1] + bb.y;
                x *= sigf(x); y *= sigf(y);
                unsigned short hx, lx, hy, ly;
                split1(x, hx, lx); split1(y, hy, ly);
                uint32_t off = r * LDSB + (uint32_t)c * 2u;
                *(uint32_t*)(sm + AHO + off) = pack2(hx, hy);
                *(uint32_t*)(sm + ALO + off) = pack2(lx, ly);
            }
        }
    cpa_wait<0>();
    __syncthreads();

    zero_acc(acc);
    gemm3(sb, B1H, B1L, warpM, warpN, lane, acc);

#pragma unroll
    for (int mt = 0; mt < 2; ++mt)
#pragma unroll
        for (int hrow = 0; hrow < 2; ++hrow) {
            int n = n0 + r0 + mt * 16 + hrow * 8;
            if (n < N) {
#pragma unroll
                for (int nidx = 0; nidx < 8; ++nidx) {
                    int c = c0b + nidx * 8;
                    float2 bb = *(const float2*)(b2 + c);
                    *(float2*)(out + (size_t)n * FDIM + c) = make_float2(
                        acc[mt][nidx][hrow * 2 + 0] + bb.x,
                        acc[mt][nidx][hrow * 2 + 1] + bb.y);
                }
            }
        }
}

__device__ void muproj_body(char* sm, const float* __restrict__ mu,
                            const __nv_bfloat16* __restrict__ imgT1,
                            const __nv_bfloat16* __restrict__ imgT2,
                            const __nv_bfloat16* __restrict__ imgT3,
                            float* __restrict__ M1, float* __restrict__ M2,
                            float* __restrict__ M3, int tileIdx, int N) {
    int tid = threadIdx.x, wid = tid >> 5, lane = tid & 31;
    int warpM = wid >> 1, warpN = wid & 1;
    int n0 = tileIdx * TILE;
    uint32_t sb = smem_u32(sm);
    int r0 = warpM * 32 + (lane >> 2);
    int c0b = warpN * 64 + (lane & 3) * 2;

    const __nv_bfloat16* imgs[3] = {imgT1, imgT2, imgT3};
    float* Ms[3] = {M1, M2, M3};

    prefetch_B(sb, B0H, B0L, imgs[0]);
    int it = 0;
    for (int c = 0; c < 3; ++c) {
        __syncthreads();
        for (int i = tid; i < TILE * FDIM; i += NTH) {
            uint32_t r = (uint32_t)(i >> 7), f = (uint32_t)(i & 127);
            float v = 0.f;
            if (n0 + (int)r < N) v = __ldg(mu + ((size_t)(n0 + r) * FDIM + f) * 3 + c);
            unsigned short h, l;
            split1(v, h, l);
            uint32_t off = r * LDSB + f * 2u;
            *(unsigned short*)(sm + AHO + off) = h;
            *(unsigned short*)(sm + ALO + off) = l;
        }
        for (int w = 0; w < 3; ++w, ++it) {
            uint32_t bho = (it & 1) ? B1H : B0H;
            uint32_t blo = (it & 1) ? B1L : B0L;
            cpa_wait<0>();
            __syncthreads();
            if (it < 8)
                prefetch_B(sb, (it & 1) ? B0H : B1H, (it & 1) ? B0L : B1L,
                           imgs[(w + 1) % 3]);
            float acc[2][8][4];
            zero_acc(acc);
            gemm3(sb, bho, blo, warpM, warpN, lane, acc);
            float* dst = Ms[w] + (size_t)c * PLANE;
#pragma unroll
            for (int mt = 0; mt < 2; ++mt)
#pragma unroll
                for (int hrow = 0; hrow < 2; ++hrow) {
                    int n = n0 + r0 + mt * 16 + hrow * 8;
                    if (n < N) {
#pragma unroll
                        for (int nidx = 0; nidx < 8; ++nidx) {
                            int cc = c0b + nidx * 8;
                            *(float2*)(dst + (size_t)n * FDIM + cc) = make_float2(
                                acc[mt][nidx][hrow * 2 + 0], acc[mt][nidx][hrow * 2 + 1]);
                        }
                    }
                }
        }
    }
}

__device__ void vproj_body(char* sm, const float* __restrict__ mv,
                           const __nv_bfloat16* __restrict__ imgV,
                           float* __restrict__ out, int tileIdx, int N) {
    int tid = threadIdx.x, wid = tid >> 5, lane = tid & 31;
    int warpM = wid >> 1, warpN = wid & 1;
    int n0 = tileIdx * TILE;
    uint32_t sb = smem_u32(sm);
    int r0 = warpM * 32 + (lane >> 2);
    int c0b = warpN * 64 + (lane & 3) * 2;

    auto prefetch_plane = [&](const float* __restrict__ src) {
        for (int i = tid; i < TILE * 32; i += NTH) {
            uint32_t r = (uint32_t)(i >> 5), q = (uint32_t)(i & 31);
            uint32_t dst = sb + VST + r * 512u + q * 16u;
            if (n0 + (int)r < N) cpa16(dst, src + (size_t)(n0 + r) * FDIM + q * 4);
            else *(uint4*)(sm + VST + r * 512u + q * 16u) = make_uint4(0, 0, 0, 0);
        }
        cpa_commit();
    };

    prefetch_B(sb, VBH, VBL, imgV);
    prefetch_plane(mv);
#pragma unroll 1
    for (int c = 0; c < 3; ++c) {
        cpa_wait<0>();
        __syncthreads();
        for (int i = tid; i < TILE * 16; i += NTH) {
            uint32_t r = (uint32_t)(i >> 4), q = (uint32_t)(i & 15);
            const float* p = (const float*)(sm + VST + r * 512u) + q * 8;
            float4 v0 = *(const float4*)p, v1 = *(const float4*)(p + 4);
            unsigned short h[8], l[8];
            split1(v0.x, h[0], l[0]); split1(v0.y, h[1], l[1]);
            split1(v0.z, h[2], l[2]); split1(v0.w, h[3], l[3]);
            split1(v1.x, h[4], l[4]); split1(v1.y, h[5], l[5]);
            split1(v1.z, h[6], l[6]); split1(v1.w, h[7], l[7]);
            uint32_t off = r * LDSB + q * 16u;
            *(uint4*)(sm + AHO + off) = make_uint4(pack2(h[0], h[1]), pack2(h[2], h[3]),
                                                   pack2(h[4], h[5]), pack2(h[6], h[7]));
            *(uint4*)(sm + ALO + off) = make_uint4(pack2(l[0], l[1]), pack2(l[2], l[3]),
                                                   pack2(l[4], l[5]), pack2(l[6], l[7]));
        }
        __syncthreads();
        if (c < 2) prefetch_plane(mv + (size_t)(c + 1) * PLANE);
        float acc[2][8][4];
        zero_acc(acc);
        gemm3(sb, VBH, VBL, warpM, warpN, lane, acc);
#pragma unroll
        for (int mt = 0; mt < 2; ++mt)
#pragma unroll
            for (int hrow = 0; hrow < 2; ++hrow) {
                int n = n0 + r0 + mt * 16 + hrow * 8;
                if (n < N) {
                    float* o = out + (size_t)n * FDIM * 3 + c;
#pragma unroll
                    for (int nidx = 0; nidx < 8; ++nidx) {
                        int a = c0b + nidx * 8;
                        o[(size_t)a * 3]       = acc[mt][nidx][hrow * 2 + 0];
                        o[(size_t)(a + 1) * 3] = acc[mt][nidx][hrow * 2 + 1];
                    }
                }
            }
    }
}

// ================= merged kernels =================
__global__ void __launch_bounds__(NTH) phase1_kernel(
    const float* __restrict__ feat, const float* __restrict__ mu,
    const __nv_bfloat16* __restrict__ imgQ1, const float* __restrict__ bq1,
    const __nv_bfloat16* __restrict__ imgQ2, const float* __restrict__ bq2,
    const __nv_bfloat16* __restrict__ imgT1, const __nv_bfloat16* __restrict__ imgT2,
    const __nv_bfloat16* __restrict__ imgT3,
    float* __restrict__ M0, float* __restrict__ M1, float* __restrict__ M2,
    float* __restrict__ M3, int N) {
    extern __shared__ char sm[];
    int b = blockIdx.x;
    if (b & 1) muproj_body(sm, mu, imgT1, imgT2, imgT3, M1, M2, M3, b >> 1, N);
    else       dense2_body(sm, feat, imgQ1, bq1, imgQ2, bq2, M0, b >> 1, N);
}

__global__ void __launch_bounds__(NTH) phase2_kernel(
    const float* __restrict__ ms, const float* __restrict__ mv,
    const __nv_bfloat16* __restrict__ imgS1, const float* __restrict__ bs1,
    const __nv_bfloat16* __restrict__ imgS2, const float* __restrict__ bs2,
    const __nv_bfloat16* __restrict__ imgV,
    float* __restrict__ ms_out, float* __restrict__ mv_out, int N) {
    extern __shared__ char sm[];
    int b = blockIdx.x;
    if (b & 1) vproj_body(sm, mv, imgV, mv_out, b >> 1, N);
    else       dense2_body(sm, ms, imgS1, bs1, imgS2, bs2, ms_out, b >> 1, N);
}

// ================= prep =================
struct WPtrs { const float* p[8]; };
__global__ void prep_weights(WPtrs wp) {
    int w = blockIdx.x;
    const float* src = wp.p[w];
    __nv_bfloat16* hi = g_Wimg[w];
    __nv_bfloat16* lo = g_Wimg[w] + 16384;
    for (int i = threadIdx.x; i < 16384; i += blockDim.x) {
        int k = i >> 7, g = i & 127;
        unsigned short h, l;
        split1(src[i], h, l);
        hi[g * 128 + k] = *(__nv_bfloat16*)&h;
        lo[g * 128 + k] = *(__nv_bfloat16*)&l;
    }
}

// ================= combine (DRAM-roofline) =================
__global__ void __launch_bounds__(FDIM) combine_kernel(
    const float* __restrict__ T0, const float* __restrict__ T1,
    const float* __restrict__ T2, const float* __restrict__ T3,
    const float* __restrict__ M0, const float* __restrict__ M1,
    const float* __restrict__ M2, const float* __restrict__ M3,
    float* __restrict__ ms, float* __restrict__ mv, int N) {
    int n = blockIdx.x;
    __shared__ float st[40];
    int tid = threadIdx.x;
    if (tid == 0) st[0] = T0[n];
    if (tid < 3) st[1 + tid] = T1[(size_t)n * 3 + tid];
    if (tid >= 32 && tid < 41) st[4 + tid - 32] = T2[(size_t)n * 9 + (tid - 32)];
    if (tid >= 64 && tid < 91) st[13 + tid - 64] = T3[(size_t)n * 27 + (tid - 64)];
    __syncthreads();

    float t0 = st[0];
    float t1[3], t2[9], t3[27];
#pragma unroll
    for (int k = 0; k < 3; ++k) t1[k] = st[1 + k];
#pragma unroll
    for (int k = 0; k < 9; ++k) t2[k] = st[4 + k];
#pragma unroll
    for (int k = 0; k < 27; ++k) t3[k] = st[13 + k];

    size_t base = (size_t)n * FDIM + tid;
    float m0 = M0[base];
    float m1[3], m2[3], m3[3];
#pragma unroll
    for (int c = 0; c < 3; ++c) {
        m1[c] = M1[base + (size_t)c * PLANE];
        m2[c] = M2[base + (size_t)c * PLANE];
        m3[c] = M3[base + (size_t)c * PLANE];
    }

    float s = t0 * m0;
#pragma unroll
    for (int i = 0; i < 3; ++i) s += m1[i] * t1[i];
#pragma unroll
    for (int i = 0; i < 3; ++i)
#pragma unroll
        for (int j = 0; j < 3; ++j) s += m2[i] * m2[j] * t2[i * 3 + j];
#pragma unroll
    for (int i = 0; i < 3; ++i) {
        float mi = m3[i];
#pragma unroll
        for (int j = 0; j < 3; ++j) {
            float mij = mi * m3[j];
#pragma unroll
            for (int k = 0; k < 3; ++k) s += mij * m3[k] * t3[i * 9 + j * 3 + k];
        }
    }
    ms[base] = s;

#pragma unroll
    for (int i = 0; i < 3; ++i) {
        float v = t1[i] * m0;
#pragma unroll
        for (int j = 0; j < 3; ++j) v += t2[i * 3 + j] * m1[j];
#pragma unroll
        for (int j = 0; j < 3; ++j)
#pragma unroll
            for (int k = 0; k < 3; ++k) v += t3[i * 9 + j * 3 + k] * m2[j] * m2[k];
        mv[base + (size_t)i * PLANE] = v;
    }
}

// ================= launch =================
extern "C" void kernel_launch(void* const* d_in, const int* in_sizes, int n_in,
                              void* d_out, int out_size) {
    const float* feat = (const float*)d_in[0];
    const float* mu   = (const float*)d_in[1];
    const float* T0   = (const float*)d_in[2];
    const float* T1   = (const float*)d_in[3];
    const float* T2   = (const float*)d_in[4];
    const float* T3   = (const float*)d_in[5];
    const float* Wq1  = (const float*)d_in[6];
    const float* bq1  = (const float*)d_in[7];
    const float* Wq2  = (const float*)d_in[8];
    const float* bq2  = (const float*)d_in[9];
    const float* WT1  = (const float*)d_in[10];
    const float* WT2  = (const float*)d_in[11];
    const float* WT3  = (const float*)d_in[12];
    const float* Ws1  = (const float*)d_in[13];
    const float* bs1  = (const float*)d_in[14];
    const float* Ws2  = (const float*)d_in[15];
    const float* bs2  = (const float*)d_in[16];
    const float* Wv   = (const float*)d_in[17];

    int N = in_sizes[0] / FDIM;
    if (N > MAXN) N = MAXN;

    float* out = (float*)d_out;
    float* ms_out = out;
    float* mv_out = out + (size_t)N * FDIM;

    cudaFuncSetAttribute(phase1_kernel, cudaFuncAttributeMaxDynamicSharedMemorySize, (int)SMSZ6);
    cudaFuncSetAttribute(phase2_kernel, cudaFuncAttributeMaxDynamicSharedMemorySize, (int)SMSZ6);

    float *pM0, *pM1, *pM2, *pM3, *pms, *pmv;
    __nv_bfloat16* pW;
    cudaGetSymbolAddress((void**)&pM0, g_M0);
    cudaGetSymbolAddress((void**)&pM1, g_M1);
    cudaGetSymbolAddress((void**)&pM2, g_M2);
    cudaGetSymbolAddress((void**)&pM3, g_M3);
    cudaGetSymbolAddress((void**)&pms, g_ms);
    cudaGetSymbolAddress((void**)&pmv, g_mv);
    cudaGetSymbolAddress((void**)&pW,  g_Wimg);

    WPtrs wp;
    wp.p[0] = Wq1; wp.p[1] = Wq2; wp.p[2] = WT1; wp.p[3] = WT2;
    wp.p[4] = WT3; wp.p[5] = Ws1; wp.p[6] = Ws2; wp.p[7] = Wv;
    prep_weights<<<8, 256>>>(wp);

    int nb = (N + TILE - 1) / TILE;
    phase1_kernel<<<2 * nb, NTH, SMSZ6>>>(feat, mu,
                                          pW + 0 * 32768, bq1, pW + 1 * 32768, bq2,
                                          pW + 2 * 32768, pW + 3 * 32768, pW + 4 * 32768,
                                          pM0, pM1, pM2, pM3, N);
    combine_kernel<<<N, FDIM>>>(T0, T1, T2, T3, pM0, pM1, pM2, pM3, pms, pmv, N);
    phase2_kernel<<<2 * nb, NTH, SMSZ6>>>(pms, pmv,
                                          pW + 5 * 32768, bs1, pW + 6 * 32768, bs2,
                                          pW + 7 * 32768, ms_out, mv_out, N);
}

// round 12
// speedup vs baseline: 1.3152x; 1.0072x over previous
#include <cuda_runtime.h>
#include <cuda_bf16.h>
#include <cstdint>
#include <math.h>

#define MAXN 50000
#define FDIM 128
#define TILE 128
#define NTH  256
#define PLANE ((size_t)MAXN * FDIM)

// padded bf16 planes: row stride 136 bf16 = 272 B (ldmatrix conflict-free)
#define LDSB 272u
#define PLB  34816u
#define AHO 0u
#define ALO PLB
#define B0H (2u*PLB)
#define B0L (3u*PLB)
#define B1H (4u*PLB)
#define B1L (5u*PLB)
#define SMSZ6 (6u*PLB)            // 208896
#define VBH (2u*PLB)
#define VBL (3u*PLB)
#define VST (4u*PLB)

// -------- scratch --------
__device__ float g_M0[MAXN * FDIM];
__device__ float g_M1[3][MAXN * FDIM];
__device__ float g_M2[3][MAXN * FDIM];
__device__ float g_M3[3][MAXN * FDIM];
__device__ float g_ms[MAXN * FDIM];
__device__ float g_mv[3][MAXN * FDIM];
__device__ __nv_bfloat16 g_Wimg[8][32768];   // [hi 16384 | lo 16384], [out][in]

// ================= helpers =================
__device__ __forceinline__ uint32_t smem_u32(const void* p) {
    uint32_t a;
    asm("{ .reg .u64 t; cvta.to.shared.u64 t, %1; cvt.u32.u64 %0, t; }" : "=r"(a) : "l"(p));
    return a;
}
__device__ __forceinline__ void cpa16(uint32_t dst, const void* src) {
    asm volatile("cp.async.cg.shared.global [%0], [%1], 16;" :: "r"(dst), "l"(src));
}
__device__ __forceinline__ void cpa_commit() { asm volatile("cp.async.commit_group;"); }
template <int K> __device__ __forceinline__ void cpa_wait() {
    asm volatile("cp.async.wait_group %0;" :: "n"(K));
}
__device__ __forceinline__ void ldm4(uint32_t* r, uint32_t addr) {
    asm volatile("ldmatrix.sync.aligned.m8n8.x4.shared.b16 {%0,%1,%2,%3}, [%4];"
                 : "=r"(r[0]), "=r"(r[1]), "=r"(r[2]), "=r"(r[3]) : "r"(addr));
}
__device__ __forceinline__ void mma16816(float* c, const uint32_t* a, uint32_t b0, uint32_t b1) {
    asm volatile(
        "mma.sync.aligned.m16n8k16.row.col.f32.bf16.bf16.f32 "
        "{%0,%1,%2,%3}, {%4,%5,%6,%7}, {%8,%9}, {%0,%1,%2,%3};"
        : "+f"(c[0]), "+f"(c[1]), "+f"(c[2]), "+f"(c[3])
        : "r"(a[0]), "r"(a[1]), "r"(a[2]), "r"(a[3]), "r"(b0), "r"(b1));
}
__device__ __forceinline__ void split1(float x, unsigned short& h, unsigned short& l) {
    __nv_bfloat16 hb = __float2bfloat16(x);
    float r = x - __bfloat162float(hb);
    __nv_bfloat16 lb = __float2bfloat16(r);
    h = *(unsigned short*)&hb;
    l = *(unsigned short*)&lb;
}
__device__ __forceinline__ uint32_t pack2(unsigned short a, unsigned short b) {
    return (uint32_t)a | ((uint32_t)b << 16);
}
__device__ __forceinline__ float sigf(float x) { return 1.f / (1.f + __expf(-x)); }

__device__ __forceinline__ void prefetch_B(uint32_t sb, uint32_t bho, uint32_t blo,
                                           const __nv_bfloat16* __restrict__ img) {
    for (int i = threadIdx.x; i < 4096; i += NTH) {
        int half = i >> 11, idx = i & 2047;
        uint32_t r = (uint32_t)(idx >> 4), q = (uint32_t)(idx & 15);
        uint32_t dst = sb + (half ? blo : bho) + r * LDSB + q * 16u;
        cpa16(dst, (const uint4*)(img + half * 16384) + idx);
    }
    cpa_commit();
}

__device__ __forceinline__ void load_split_A(char* sm, const float* __restrict__ src,
                                             int n0, int N) {
    for (int i = threadIdx.x; i < TILE * 16; i += NTH) {
        uint32_t r = (uint32_t)(i >> 4), q = (uint32_t)(i & 15);
        float4 v0 = make_float4(0.f, 0.f, 0.f, 0.f), v1 = v0;
        if (n0 + (int)r < N) {
            const float* p = src + (size_t)(n0 + r) * FDIM + q * 8;
            v0 = *(const float4*)p;
            v1 = *(const float4*)(p + 4);
        }
        unsigned short h[8], l[8];
        split1(v0.x, h[0], l[0]); split1(v0.y, h[1], l[1]);
        split1(v0.z, h[2], l[2]); split1(v0.w, h[3], l[3]);
        split1(v1.x, h[4], l[4]); split1(v1.y, h[5], l[5]);
        split1(v1.z, h[6], l[6]); split1(v1.w, h[7], l[7]);
        uint32_t off = r * LDSB + q * 16u;
        *(uint4*)(sm + AHO + off) = make_uint4(pack2(h[0], h[1]), pack2(h[2], h[3]),
                                               pack2(h[4], h[5]), pack2(h[6], h[7]));
        *(uint4*)(sm + ALO + off) = make_uint4(pack2(l[0], l[1]), pack2(l[2], l[3]),
                                               pack2(l[4], l[5]), pack2(l[6], l[7]));
    }
}

// ---- 3-term split GEMM: shared fragments, TERM-MAJOR MMA order ----
// 8 warps: grid 4(M)x2(N), warp tile 32x64; acc[mt2][nidx8][4]
// Per k-chunk: 12 ldm4, then 3 passes of 16 MMAs over all 16 accumulators
// -> 16 independent RAW chains (vs 2 in the pairwise order).
__device__ __forceinline__ void gemm3(uint32_t sb, uint32_t bho, uint32_t blo,
                                      int warpM, int warpN, int lane, float acc[2][8][4]) {
    uint32_t rowA = (uint32_t)(warpM * 32 + (lane & 15)) * LDSB;
    uint32_t rowB = (uint32_t)(warpN * 64 + (lane & 15)) * LDSB;
    uint32_t kh = (uint32_t)((lane >> 4) * 8) * 2u;
#pragma unroll
    for (int kc = 0; kc < 8; ++kc) {
        uint32_t kof = kh + (uint32_t)kc * 32u;
        uint32_t ah[2][4], al[2][4], bh[4][4], bl[4][4];
#pragma unroll
        for (int mt = 0; mt < 2; ++mt) {
            uint32_t a = rowA + (uint32_t)(mt * 16) * LDSB + kof;
            ldm4(ah[mt], sb + AHO + a);
            ldm4(al[mt], sb + ALO + a);
        }
#pragma unroll
        for (int nt = 0; nt < 4; ++nt) {
            uint32_t b = rowB + (uint32_t)(nt * 16) * LDSB + kof;
            ldm4(bh[nt], sb + bho + b);
            ldm4(bl[nt], sb + blo + b);
        }
        // term 1: Ah * Bh  (16 MMAs, all distinct accumulators)
#pragma unroll
        for (int mt = 0; mt < 2; ++mt)
#pragma unroll
            for (int nt = 0; nt < 4; ++nt) {
                mma16816(acc[mt][nt * 2 + 0], ah[mt], bh[nt][0], bh[nt][2]);
                mma16816(acc[mt][nt * 2 + 1], ah[mt], bh[nt][1], bh[nt][3]);
            }
        // term 2: Ah * Bl
#pragma unroll
        for (int mt = 0; mt < 2; ++mt)
#pragma unroll
            for (int nt = 0; nt < 4; ++nt) {
                mma16816(acc[mt][nt * 2 + 0], ah[mt], bl[nt][0], bl[nt][2]);
                mma16816(acc[mt][nt * 2 + 1], ah[mt], bl[nt][1], bl[nt][3]);
            }
        // term 3: Al * Bh
#pragma unroll
        for (int mt = 0; mt < 2; ++mt)
#pragma unroll
            for (int nt = 0; nt < 4; ++nt) {
                mma16816(acc[mt][nt * 2 + 0], al[mt], bh[nt][0], bh[nt][2]);
                mma16816(acc[mt][nt * 2 + 1], al[mt], bh[nt][1], bh[nt][3]);
            }
    }
}
__device__ __forceinline__ void zero_acc(float acc[2][8][4]) {
#pragma unroll
    for (int m = 0; m < 2; ++m)
#pragma unroll
        for (int n = 0; n < 8; ++n)
#pragma unroll
            for (int j = 0; j < 4; ++j) acc[m][n][j] = 0.f;
}

// ================= device bodies =================
__device__ void dense2_body(char* sm, const float* __restrict__ in,
                            const __nv_bfloat16* __restrict__ img1, const float* __restrict__ b1,
                            const __nv_bfloat16* __restrict__ img2, const float* __restrict__ b2,
                            float* __restrict__ out, int tileIdx, int N) {
    int tid = threadIdx.x, wid = tid >> 5, lane = tid & 31;
    int warpM = wid >> 1, warpN = wid & 1;
    int n0 = tileIdx * TILE;
    uint32_t sb = smem_u32(sm);
    int r0 = warpM * 32 + (lane >> 2);
    int c0b = warpN * 64 + (lane & 3) * 2;

    prefetch_B(sb, B0H, B0L, img1);
    prefetch_B(sb, B1H, B1L, img2);
    load_split_A(sm, in, n0, N);
    cpa_wait<1>();
    __syncthreads();

    float acc[2][8][4];
    zero_acc(acc);
    gemm3(sb, B0H, B0L, warpM, warpN, lane, acc);
    __syncthreads();

#pragma unroll
    for (int mt = 0; mt < 2; ++mt)
#pragma unroll
        for (int nidx = 0; nidx < 8; ++nidx) {
            int c = c0b + nidx * 8;
            float2 bb = *(const float2*)(b1 + c);
#pragma unroll
            for (int hrow = 0; hrow < 2; ++hrow) {
                uint32_t r = (uint32_t)(r0 + mt * 16 + hrow * 8);
                float x = acc[mt][nidx][hrow * 2 + 0] + bb.x;
                float y = acc[mt][nidx][hrow * 2 + 1] + bb.y;
                x *= sigf(x); y *= sigf(y);
                unsigned short hx, lx, hy, ly;
                split1(x, hx, lx); split1(y, hy, ly);
                uint32_t off = r * LDSB + (uint32_t)c * 2u;
                *(uint32_t*)(sm + AHO + off) = pack2(hx, hy);
                *(uint32_t*)(sm + ALO + off) = pack2(lx, ly);
            }
        }
    cpa_wait<0>();
    __syncthreads();

    zero_acc(acc);
    gemm3(sb, B1H, B1L, warpM, warpN, lane, acc);

#pragma unroll
    for (int mt = 0; mt < 2; ++mt)
#pragma unroll
        for (int hrow = 0; hrow < 2; ++hrow) {
            int n = n0 + r0 + mt * 16 + hrow * 8;
            if (n < N) {
#pragma unroll
                for (int nidx = 0; nidx < 8; ++nidx) {
                    int c = c0b + nidx * 8;
                    float2 bb = *(const float2*)(b2 + c);
                    *(float2*)(out + (size_t)n * FDIM + c) = make_float2(
                        acc[mt][nidx][hrow * 2 + 0] + bb.x,
                        acc[mt][nidx][hrow * 2 + 1] + bb.y);
                }
            }
        }
}

__device__ void muproj_body(char* sm, const float* __restrict__ mu,
                            const __nv_bfloat16* __restrict__ imgT1,
                            const __nv_bfloat16* __restrict__ imgT2,
                            const __nv_bfloat16* __restrict__ imgT3,
                            float* __restrict__ M1, float* __restrict__ M2,
                            float* __restrict__ M3, int tileIdx, int N) {
    int tid = threadIdx.x, wid = tid >> 5, lane = tid & 31;
    int warpM = wid >> 1, warpN = wid & 1;
    int n0 = tileIdx * TILE;
    uint32_t sb = smem_u32(sm);
    int r0 = warpM * 32 + (lane >> 2);
    int c0b = warpN * 64 + (lane & 3) * 2;

    const __nv_bfloat16* imgs[3] = {imgT1, imgT2, imgT3};
    float* Ms[3] = {M1, M2, M3};

    prefetch_B(sb, B0H, B0L, imgs[0]);
    int it = 0;
    for (int c = 0; c < 3; ++c) {
        __syncthreads();
        for (int i = tid; i < TILE * FDIM; i += NTH) {
            uint32_t r = (uint32_t)(i >> 7), f = (uint32_t)(i & 127);
            float v = 0.f;
            if (n0 + (int)r < N) v = __ldg(mu + ((size_t)(n0 + r) * FDIM + f) * 3 + c);
            unsigned short h, l;
            split1(v, h, l);
            uint32_t off = r * LDSB + f * 2u;
            *(unsigned short*)(sm + AHO + off) = h;
            *(unsigned short*)(sm + ALO + off) = l;
        }
        for (int w = 0; w < 3; ++w, ++it) {
            uint32_t bho = (it & 1) ? B1H : B0H;
            uint32_t blo = (it & 1) ? B1L : B0L;
            cpa_wait<0>();
            __syncthreads();
            if (it < 8)
                prefetch_B(sb, (it & 1) ? B0H : B1H, (it & 1) ? B0L : B1L,
                           imgs[(w + 1) % 3]);
            float acc[2][8][4];
            zero_acc(acc);
            gemm3(sb, bho, blo, warpM, warpN, lane, acc);
            float* dst = Ms[w] + (size_t)c * PLANE;
#pragma unroll
            for (int mt = 0; mt < 2; ++mt)
#pragma unroll
                for (int hrow = 0; hrow < 2; ++hrow) {
                    int n = n0 + r0 + mt * 16 + hrow * 8;
                    if (n < N) {
#pragma unroll
                        for (int nidx = 0; nidx < 8; ++nidx) {
                            int cc = c0b + nidx * 8;
                            *(float2*)(dst + (size_t)n * FDIM + cc) = make_float2(
                                acc[mt][nidx][hrow * 2 + 0], acc[mt][nidx][hrow * 2 + 1]);
                        }
                    }
                }
        }
    }
}

__device__ void vproj_body(char* sm, const float* __restrict__ mv,
                           const __nv_bfloat16* __restrict__ imgV,
                           float* __restrict__ out, int tileIdx, int N) {
    int tid = threadIdx.x, wid = tid >> 5, lane = tid & 31;
    int warpM = wid >> 1, warpN = wid & 1;
    int n0 = tileIdx * TILE;
    uint32_t sb = smem_u32(sm);
    int r0 = warpM * 32 + (lane >> 2);
    int c0b = warpN * 64 + (lane & 3) * 2;

    auto prefetch_plane = [&](const float* __restrict__ src) {
        for (int i = tid; i < TILE * 32; i += NTH) {
            uint32_t r = (uint32_t)(i >> 5), q = (uint32_t)(i & 31);
            uint32_t dst = sb + VST + r * 512u + q * 16u;
            if (n0 + (int)r < N) cpa16(dst, src + (size_t)(n0 + r) * FDIM + q * 4);
            else *(uint4*)(sm + VST + r * 512u + q * 16u) = make_uint4(0, 0, 0, 0);
        }
        cpa_commit();
    };

    prefetch_B(sb, VBH, VBL, imgV);
    prefetch_plane(mv);
#pragma unroll 1
    for (int c = 0; c < 3; ++c) {
        cpa_wait<0>();
        __syncthreads();
        for (int i = tid; i < TILE * 16; i += NTH) {
            uint32_t r = (uint32_t)(i >> 4), q = (uint32_t)(i & 15);
            const float* p = (const float*)(sm + VST + r * 512u) + q * 8;
            float4 v0 = *(const float4*)p, v1 = *(const float4*)(p + 4);
            unsigned short h[8], l[8];
            split1(v0.x, h[0], l[0]); split1(v0.y, h[1], l[1]);
            split1(v0.z, h[2], l[2]); split1(v0.w, h[3], l[3]);
            split1(v1.x, h[4], l[4]); split1(v1.y, h[5], l[5]);
            split1(v1.z, h[6], l[6]); split1(v1.w, h[7], l[7]);
            uint32_t off = r * LDSB + q * 16u;
            *(uint4*)(sm + AHO + off) = make_uint4(pack2(h[0], h[1]), pack2(h[2], h[3]),
                                                   pack2(h[4], h[5]), pack2(h[6], h[7]));
            *(uint4*)(sm + ALO + off) = make_uint4(pack2(l[0], l[1]), pack2(l[2], l[3]),
                                                   pack2(l[4], l[5]), pack2(l[6], l[7]));
        }
        __syncthreads();
        if (c < 2) prefetch_plane(mv + (size_t)(c + 1) * PLANE);
        float acc[2][8][4];
        zero_acc(acc);
        gemm3(sb, VBH, VBL, warpM, warpN, lane, acc);
#pragma unroll
        for (int mt = 0; mt < 2; ++mt)
#pragma unroll
            for (int hrow = 0; hrow < 2; ++hrow) {
                int n = n0 + r0 + mt * 16 + hrow * 8;
                if (n < N) {
                    float* o = out + (size_t)n * FDIM * 3 + c;
#pragma unroll
                    for (int nidx = 0; nidx < 8; ++nidx) {
                        int a = c0b + nidx * 8;
                        o[(size_t)a * 3]       = acc[mt][nidx][hrow * 2 + 0];
                        o[(size_t)(a + 1) * 3] = acc[mt][nidx][hrow * 2 + 1];
                    }
                }
            }
    }
}

// ================= merged kernels =================
__global__ void __launch_bounds__(NTH) phase1_kernel(
    const float* __restrict__ feat, const float* __restrict__ mu,
    const __nv_bfloat16* __restrict__ imgQ1, const float* __restrict__ bq1,
    const __nv_bfloat16* __restrict__ imgQ2, const float* __restrict__ bq2,
    const __nv_bfloat16* __restrict__ imgT1, const __nv_bfloat16* __restrict__ imgT2,
    const __nv_bfloat16* __restrict__ imgT3,
    float* __restrict__ M0, float* __restrict__ M1, float* __restrict__ M2,
    float* __restrict__ M3, int N) {
    extern __shared__ char sm[];
    int b = blockIdx.x;
    if (b & 1) muproj_body(sm, mu, imgT1, imgT2, imgT3, M1, M2, M3, b >> 1, N);
    else       dense2_body(sm, feat, imgQ1, bq1, imgQ2, bq2, M0, b >> 1, N);
}

__global__ void __launch_bounds__(NTH) phase2_kernel(
    const float* __restrict__ ms, const float* __restrict__ mv,
    const __nv_bfloat16* __restrict__ imgS1, const float* __restrict__ bs1,
    const __nv_bfloat16* __restrict__ imgS2, const float* __restrict__ bs2,
    const __nv_bfloat16* __restrict__ imgV,
    float* __restrict__ ms_out, float* __restrict__ mv_out, int N) {
    extern __shared__ char sm[];
    int b = blockIdx.x;
    if (b & 1) vproj_body(sm, mv, imgV, mv_out, b >> 1, N);
    else       dense2_body(sm, ms, imgS1, bs1, imgS2, bs2, ms_out, b >> 1, N);
}

// ================= prep =================
struct WPtrs { const float* p[8]; };
__global__ void prep_weights(WPtrs wp) {
    int w = blockIdx.x;
    const float* src = wp.p[w];
    __nv_bfloat16* hi = g_Wimg[w];
    __nv_bfloat16* lo = g_Wimg[w] + 16384;
    for (int i = threadIdx.x; i < 16384; i += blockDim.x) {
        int k = i >> 7, g = i & 127;
        unsigned short h, l;
        split1(src[i], h, l);
        hi[g * 128 + k] = *(__nv_bfloat16*)&h;
        lo[g * 128 + k] = *(__nv_bfloat16*)&l;
    }
}

// ================= combine (DRAM-roofline) =================
__global__ void __launch_bounds__(FDIM) combine_kernel(
    const float* __restrict__ T0, const float* __restrict__ T1,
    const float* __restrict__ T2, const float* __restrict__ T3,
    const float* __restrict__ M0, const float* __restrict__ M1,
    const float* __restrict__ M2, const float* __restrict__ M3,
    float* __restrict__ ms, float* __restrict__ mv, int N) {
    int n = blockIdx.x;
    __shared__ float st[40];
    int tid = threadIdx.x;
    if (tid == 0) st[0] = T0[n];
    if (tid < 3) st[1 + tid] = T1[(size_t)n * 3 + tid];
    if (tid >= 32 && tid < 41) st[4 + tid - 32] = T2[(size_t)n * 9 + (tid - 32)];
    if (tid >= 64 && tid < 91) st[13 + tid - 64] = T3[(size_t)n * 27 + (tid - 64)];
    __syncthreads();

    float t0 = st[0];
    float t1[3], t2[9], t3[27];
#pragma unroll
    for (int k = 0; k < 3; ++k) t1[k] = st[1 + k];
#pragma unroll
    for (int k = 0; k < 9; ++k) t2[k] = st[4 + k];
#pragma unroll
    for (int k = 0; k < 27; ++k) t3[k] = st[13 + k];

    size_t base = (size_t)n * FDIM + tid;
    float m0 = M0[base];
    float m1[3], m2[3], m3[3];
#pragma unroll
    for (int c = 0; c < 3; ++c) {
        m1[c] = M1[base + (size_t)c * PLANE];
        m2[c] = M2[base + (size_t)c * PLANE];
        m3[c] = M3[base + (size_t)c * PLANE];
    }

    float s = t0 * m0;
#pragma unroll
    for (int i = 0; i < 3; ++i) s += m1[i] * t1[i];
#pragma unroll
    for (int i = 0; i < 3; ++i)
#pragma unroll
        for (int j = 0; j < 3; ++j) s += m2[i] * m2[j] * t2[i * 3 + j];
#pragma unroll
    for (int i = 0; i < 3; ++i) {
        float mi = m3[i];
#pragma unroll
        for (int j = 0; j < 3; ++j) {
            float mij = mi * m3[j];
#pragma unroll
            for (int k = 0; k < 3; ++k) s += mij * m3[k] * t3[i * 9 + j * 3 + k];
        }
    }
    ms[base] = s;

#pragma unroll
    for (int i = 0; i < 3; ++i) {
        float v = t1[i] * m0;
#pragma unroll
        for (int j = 0; j < 3; ++j) v += t2[i * 3 + j] * m1[j];
#pragma unroll
        for (int j = 0; j < 3; ++j)
#pragma unroll
            for (int k = 0; k < 3; ++k) v += t3[i * 9 + j * 3 + k] * m2[j] * m2[k];
        mv[base + (size_t)i * PLANE] = v;
    }
}

// ================= launch =================
extern "C" void kernel_launch(void* const* d_in, const int* in_sizes, int n_in,
                              void* d_out, int out_size) {
    const float* feat = (const float*)d_in[0];
    const float* mu   = (const float*)d_in[1];
    const float* T0   = (const float*)d_in[2];
    const float* T1   = (const float*)d_in[3];
    const float* T2   = (const float*)d_in[4];
    const float* T3   = (const float*)d_in[5];
    const float* Wq1  = (const float*)d_in[6];
    const float* bq1  = (const float*)d_in[7];
    const float* Wq2  = (const float*)d_in[8];
    const float* bq2  = (const float*)d_in[9];
    const float* WT1  = (const float*)d_in[10];
    const float* WT2  = (const float*)d_in[11];
    const float* WT3  = (const float*)d_in[12];
    const float* Ws1  = (const float*)d_in[13];
    const float* bs1  = (const float*)d_in[14];
    const float* Ws2  = (const float*)d_in[15];
    const float* bs2  = (const float*)d_in[16];
    const float* Wv   = (const float*)d_in[17];

    int N = in_sizes[0] / FDIM;
    if (N > MAXN) N = MAXN;

    float* out = (float*)d_out;
    float* ms_out = out;
    float* mv_out = out + (size_t)N * FDIM;

    cudaFuncSetAttribute(phase1_kernel, cudaFuncAttributeMaxDynamicSharedMemorySize, (int)SMSZ6);
    cudaFuncSetAttribute(phase2_kernel, cudaFuncAttributeMaxDynamicSharedMemorySize, (int)SMSZ6);

    float *pM0, *pM1, *pM2, *pM3, *pms, *pmv;
    __nv_bfloat16* pW;
    cudaGetSymbolAddress((void**)&pM0, g_M0);
    cudaGetSymbolAddress((void**)&pM1, g_M1);
    cudaGetSymbolAddress((void**)&pM2, g_M2);
    cudaGetSymbolAddress((void**)&pM3, g_M3);
    cudaGetSymbolAddress((void**)&pms, g_ms);
    cudaGetSymbolAddress((void**)&pmv, g_mv);
    cudaGetSymbolAddress((void**)&pW,  g_Wimg);

    WPtrs wp;
    wp.p[0] = Wq1; wp.p[1] = Wq2; wp.p[2] = WT1; wp.p[3] = WT2;
    wp.p[4] = WT3; wp.p[5] = Ws1; wp.p[6] = Ws2; wp.p[7] = Wv;
    prep_weights<<<8, 256>>>(wp);

    int nb = (N + TILE - 1) / TILE;
    phase1_kernel<<<2 * nb, NTH, SMSZ6>>>(feat, mu,
                                          pW + 0 * 32768, bq1, pW + 1 * 32768, bq2,
                                          pW + 2 * 32768, pW + 3 * 32768, pW + 4 * 32768,
                                          pM0, pM1, pM2, pM3, N);
    combine_kernel<<<N, FDIM>>>(T0, T1, T2, T3, pM0, pM1, pM2, pM3, pms, pmv, N);
    phase2_kernel<<<2 * nb, NTH, SMSZ6>>>(pms, pmv,
                                          pW + 5 * 32768, bs1, pW + 6 * 32768, bs2,
                                          pW + 7 * 32768, ms_out, mv_out, N);
}

// round 13
// speedup vs baseline: 1.3476x; 1.0246x over previous
#include <cuda_runtime.h>
#include <cuda_bf16.h>
#include <cstdint>
#include <math.h>

#define MAXN 50000
#define FDIM 128
#define TILE 128
#define NTH  256
#define PLANE ((size_t)MAXN * FDIM)

// ---- dense2: padded layout (272B rows), 208 KB, 1 CTA/SM ----
#define LDSB 272u
#define PLB  34816u
#define AHO 0u
#define ALO PLB
#define B0H (2u*PLB)
#define B0L (3u*PLB)
#define B1H (4u*PLB)
#define B1L (5u*PLB)
#define SMSZ6 (6u*PLB)            // 208896

// ---- split kernels: XOR-swizzled layout (256B rows), 96 KB, 2 CTA/SM ----
#define SAH 0u
#define SAL 32768u
#define SBH 65536u
#define SBL 81920u
#define SMSZH 98304

// -------- scratch --------
__device__ float g_M0[MAXN * FDIM];
__device__ float g_M1[3][MAXN * FDIM];
__device__ float g_M2[3][MAXN * FDIM];
__device__ float g_M3[3][MAXN * FDIM];
__device__ float g_ms[MAXN * FDIM];
__device__ float g_mv[3][MAXN * FDIM];
__device__ __nv_bfloat16 g_Wimg[8][32768];   // [hi 16384 | lo 16384], [out][in]

// ================= helpers =================
__device__ __forceinline__ uint32_t smem_u32(const void* p) {
    uint32_t a;
    asm("{ .reg .u64 t; cvta.to.shared.u64 t, %1; cvt.u32.u64 %0, t; }" : "=r"(a) : "l"(p));
    return a;
}
__device__ __forceinline__ uint32_t swz(uint32_t r, uint32_t q) {   // 256B rows, 16B chunks
    return (r << 8) + ((q ^ (r & 7u)) << 4);
}
__device__ __forceinline__ void cpa16(uint32_t dst, const void* src) {
    asm volatile("cp.async.cg.shared.global [%0], [%1], 16;" :: "r"(dst), "l"(src));
}
__device__ __forceinline__ void cpa_commit() { asm volatile("cp.async.commit_group;"); }
template <int K> __device__ __forceinline__ void cpa_wait() {
    asm volatile("cp.async.wait_group %0;" :: "n"(K));
}
__device__ __forceinline__ void ldm4(uint32_t* r, uint32_t addr) {
    asm volatile("ldmatrix.sync.aligned.m8n8.x4.shared.b16 {%0,%1,%2,%3}, [%4];"
                 : "=r"(r[0]), "=r"(r[1]), "=r"(r[2]), "=r"(r[3]) : "r"(addr));
}
__device__ __forceinline__ void mma16816(float* c, const uint32_t* a, uint32_t b0, uint32_t b1) {
    asm volatile(
        "mma.sync.aligned.m16n8k16.row.col.f32.bf16.bf16.f32 "
        "{%0,%1,%2,%3}, {%4,%5,%6,%7}, {%8,%9}, {%0,%1,%2,%3};"
        : "+f"(c[0]), "+f"(c[1]), "+f"(c[2]), "+f"(c[3])
        : "r"(a[0]), "r"(a[1]), "r"(a[2]), "r"(a[3]), "r"(b0), "r"(b1));
}
__device__ __forceinline__ void split1(float x, unsigned short& h, unsigned short& l) {
    __nv_bfloat16 hb = __float2bfloat16(x);
    float r = x - __bfloat162float(hb);
    __nv_bfloat16 lb = __float2bfloat16(r);
    h = *(unsigned short*)&hb;
    l = *(unsigned short*)&lb;
}
__device__ __forceinline__ uint32_t pack2(unsigned short a, unsigned short b) {
    return (uint32_t)a | ((uint32_t)b << 16);
}
__device__ __forceinline__ float sigf(float x) { return 1.f / (1.f + __expf(-x)); }

// ================= dense2 pieces (padded layout, unchanged from 587us kernel) =================
__device__ __forceinline__ void prefetch_B_pad(uint32_t sb, uint32_t bho, uint32_t blo,
                                               const __nv_bfloat16* __restrict__ img) {
    for (int i = threadIdx.x; i < 4096; i += NTH) {
        int half = i >> 11, idx = i & 2047;
        uint32_t r = (uint32_t)(idx >> 4), q = (uint32_t)(idx & 15);
        uint32_t dst = sb + (half ? blo : bho) + r * LDSB + q * 16u;
        cpa16(dst, (const uint4*)(img + half * 16384) + idx);
    }
    cpa_commit();
}
__device__ __forceinline__ void load_split_A_pad(char* sm, const float* __restrict__ src,
                                                 int n0, int N) {
    for (int i = threadIdx.x; i < TILE * 16; i += NTH) {
        uint32_t r = (uint32_t)(i >> 4), q = (uint32_t)(i & 15);
        float4 v0 = make_float4(0.f, 0.f, 0.f, 0.f), v1 = v0;
        if (n0 + (int)r < N) {
            const float* p = src + (size_t)(n0 + r) * FDIM + q * 8;
            v0 = *(const float4*)p;
            v1 = *(const float4*)(p + 4);
        }
        unsigned short h[8], l[8];
        split1(v0.x, h[0], l[0]); split1(v0.y, h[1], l[1]);
        split1(v0.z, h[2], l[2]); split1(v0.w, h[3], l[3]);
        split1(v1.x, h[4], l[4]); split1(v1.y, h[5], l[5]);
        split1(v1.z, h[6], l[6]); split1(v1.w, h[7], l[7]);
        uint32_t off = r * LDSB + q * 16u;
        *(uint4*)(sm + AHO + off) = make_uint4(pack2(h[0], h[1]), pack2(h[2], h[3]),
                                               pack2(h[4], h[5]), pack2(h[6], h[7]));
        *(uint4*)(sm + ALO + off) = make_uint4(pack2(l[0], l[1]), pack2(l[2], l[3]),
                                               pack2(l[4], l[5]), pack2(l[6], l[7]));
    }
}
// 8 warps, grid 4x2, warp tile 32x64 (the proven R8 core)
__device__ __forceinline__ void gemm3_pad(uint32_t sb, uint32_t bho, uint32_t blo,
                                          int warpM, int warpN, int lane, float acc[2][8][4]) {
    uint32_t rowA = (uint32_t)(warpM * 32 + (lane & 15)) * LDSB;
    uint32_t rowB = (uint32_t)(warpN * 64 + (lane & 15)) * LDSB;
    uint32_t kh = (uint32_t)((lane >> 4) * 8) * 2u;
#pragma unroll
    for (int kc = 0; kc < 8; ++kc) {
        uint32_t kof = kh + (uint32_t)kc * 32u;
        uint32_t ah[2][4], al[2][4], bh[4][4], bl[4][4];
#pragma unroll
        for (int mt = 0; mt < 2; ++mt) {
            uint32_t a = rowA + (uint32_t)(mt * 16) * LDSB + kof;
            ldm4(ah[mt], sb + AHO + a);
            ldm4(al[mt], sb + ALO + a);
        }
#pragma unroll
        for (int nt = 0; nt < 4; ++nt) {
            uint32_t b = rowB + (uint32_t)(nt * 16) * LDSB + kof;
            ldm4(bh[nt], sb + bho + b);
            ldm4(bl[nt], sb + blo + b);
        }
#pragma unroll
        for (int mt = 0; mt < 2; ++mt)
#pragma unroll
            for (int nt = 0; nt < 4; ++nt) {
                mma16816(acc[mt][nt * 2 + 0], ah[mt], bh[nt][0], bh[nt][2]);
                mma16816(acc[mt][nt * 2 + 1], ah[mt], bh[nt][1], bh[nt][3]);
                mma16816(acc[mt][nt * 2 + 0], ah[mt], bl[nt][0], bl[nt][2]);
                mma16816(acc[mt][nt * 2 + 1], ah[mt], bl[nt][1], bl[nt][3]);
                mma16816(acc[mt][nt * 2 + 0], al[mt], bh[nt][0], bh[nt][2]);
                mma16816(acc[mt][nt * 2 + 1], al[mt], bh[nt][1], bh[nt][3]);
            }
    }
}

__global__ void __launch_bounds__(NTH) dense2_mma_kernel(
    const float* __restrict__ in,
    const __nv_bfloat16* __restrict__ img1, const float* __restrict__ b1,
    const __nv_bfloat16* __restrict__ img2, const float* __restrict__ b2,
    float* __restrict__ out, int N) {
    extern __shared__ char sm[];
    int tid = threadIdx.x, wid = tid >> 5, lane = tid & 31;
    int warpM = wid >> 1, warpN = wid & 1;
    int n0 = blockIdx.x * TILE;
    uint32_t sb = smem_u32(sm);
    int r0 = warpM * 32 + (lane >> 2);
    int c0b = warpN * 64 + (lane & 3) * 2;

    prefetch_B_pad(sb, B0H, B0L, img1);
    prefetch_B_pad(sb, B1H, B1L, img2);
    load_split_A_pad(sm, in, n0, N);
    cpa_wait<1>();
    __syncthreads();

    float acc[2][8][4];
#pragma unroll
    for (int m = 0; m < 2; ++m)
#pragma unroll
        for (int n = 0; n < 8; ++n)
#pragma unroll
            for (int j = 0; j < 4; ++j) acc[m][n][j] = 0.f;
    gemm3_pad(sb, B0H, B0L, warpM, warpN, lane, acc);
    __syncthreads();

#pragma unroll
    for (int mt = 0; mt < 2; ++mt)
#pragma unroll
        for (int nidx = 0; nidx < 8; ++nidx) {
            int c = c0b + nidx * 8;
            float2 bb = *(const float2*)(b1 + c);
#pragma unroll
            for (int hrow = 0; hrow < 2; ++hrow) {
                uint32_t r = (uint32_t)(r0 + mt * 16 + hrow * 8);
                float x = acc[mt][nidx][hrow * 2 + 0] + bb.x;
                float y = acc[mt][nidx][hrow * 2 + 1] + bb.y;
                x *= sigf(x); y *= sigf(y);
                unsigned short hx, lx, hy, ly;
                split1(x, hx, lx); split1(y, hy, ly);
                uint32_t off = r * LDSB + (uint32_t)c * 2u;
                *(uint32_t*)(sm + AHO + off) = pack2(hx, hy);
                *(uint32_t*)(sm + ALO + off) = pack2(lx, ly);
            }
        }
    cpa_wait<0>();
    __syncthreads();

#pragma unroll
    for (int m = 0; m < 2; ++m)
#pragma unroll
        for (int n = 0; n < 8; ++n)
#pragma unroll
            for (int j = 0; j < 4; ++j) acc[m][n][j] = 0.f;
    gemm3_pad(sb, B1H, B1L, warpM, warpN, lane, acc);

#pragma unroll
    for (int mt = 0; mt < 2; ++mt)
#pragma unroll
        for (int hrow = 0; hrow < 2; ++hrow) {
            int n = n0 + r0 + mt * 16 + hrow * 8;
            if (n < N) {
#pragma unroll
                for (int nidx = 0; nidx < 8; ++nidx) {
                    int c = c0b + nidx * 8;
                    float2 bb = *(const float2*)(b2 + c);
                    *(float2*)(out + (size_t)n * FDIM + c) = make_float2(
                        acc[mt][nidx][hrow * 2 + 0] + bb.x,
                        acc[mt][nidx][hrow * 2 + 1] + bb.y);
                }
            }
        }
}

// ================= split-kernel core: warp tile 32x32, grid 4(M)x2(N), N=64 per CTA =================
__device__ __forceinline__ void gemm3_half(uint32_t sb, int warpM, int warpN, int lane,
                                           float acc[2][4][4]) {
    uint32_t arow = (uint32_t)(warpM * 32 + (lane & 15));
    uint32_t brow = (uint32_t)(warpN * 32 + (lane & 15));
    uint32_t qb = (uint32_t)(lane >> 4);
#pragma unroll
    for (int kc = 0; kc < 8; ++kc) {
        uint32_t q = (uint32_t)(kc * 2) + qb;
        uint32_t ah[2][4], al[2][4], bh[2][4], bl[2][4];
#pragma unroll
        for (int mt = 0; mt < 2; ++mt) {
            uint32_t off = swz(arow + (uint32_t)(mt * 16), q);
            ldm4(ah[mt], sb + SAH + off);
            ldm4(al[mt], sb + SAL + off);
        }
#pragma unroll
        for (int nt = 0; nt < 2; ++nt) {
            uint32_t off = swz(brow + (uint32_t)(nt * 16), q);
            ldm4(bh[nt], sb + SBH + off);
            ldm4(bl[nt], sb + SBL + off);
        }
#pragma unroll
        for (int mt = 0; mt < 2; ++mt)
#pragma unroll
            for (int nt = 0; nt < 2; ++nt) {
                mma16816(acc[mt][nt * 2 + 0], ah[mt], bh[nt][0], bh[nt][2]);
                mma16816(acc[mt][nt * 2 + 1], ah[mt], bh[nt][1], bh[nt][3]);
                mma16816(acc[mt][nt * 2 + 0], ah[mt], bl[nt][0], bl[nt][2]);
                mma16816(acc[mt][nt * 2 + 1], ah[mt], bl[nt][1], bl[nt][3]);
                mma16816(acc[mt][nt * 2 + 0], al[mt], bh[nt][0], bh[nt][2]);
                mma16816(acc[mt][nt * 2 + 1], al[mt], bh[nt][1], bh[nt][3]);
            }
    }
}
__device__ __forceinline__ void zero_acc_h(float acc[2][4][4]) {
#pragma unroll
    for (int m = 0; m < 2; ++m)
#pragma unroll
        for (int n = 0; n < 4; ++n)
#pragma unroll
            for (int j = 0; j < 4; ++j) acc[m][n][j] = 0.f;
}
// async copy of one HALF weight image (64 rows, hi+lo) into swizzled B planes
__device__ __forceinline__ void prefetch_B_half(uint32_t sb, const __nv_bfloat16* __restrict__ img,
                                                int h0) {
    for (int i = threadIdx.x; i < 2048; i += NTH) {
        int half = i >> 10, idx = i & 1023;
        uint32_t r = (uint32_t)(idx >> 4), q = (uint32_t)(idx & 15);
        const uint4* src = (const uint4*)(img + half * 16384 + (size_t)(h0 + r) * 128) + q;
        uint32_t dst = sb + (half ? SBL : SBH) + swz(r, q);
        cpa16(dst, src);
    }
    cpa_commit();
}
// load fp32 [128][128] from gmem, split into swizzled A planes
__device__ __forceinline__ void load_split_A_swz(char* sm, const float* __restrict__ src,
                                                 int n0, int N) {
    for (int i = threadIdx.x; i < TILE * 16; i += NTH) {
        uint32_t r = (uint32_t)(i >> 4), q = (uint32_t)(i & 15);
        float4 v0 = make_float4(0.f, 0.f, 0.f, 0.f), v1 = v0;
        if (n0 + (int)r < N) {
            const float* p = src + (size_t)(n0 + r) * FDIM + q * 8;
            v0 = *(const float4*)p;
            v1 = *(const float4*)(p + 4);
        }
        unsigned short h[8], l[8];
        split1(v0.x, h[0], l[0]); split1(v0.y, h[1], l[1]);
        split1(v0.z, h[2], l[2]); split1(v0.w, h[3], l[3]);
        split1(v1.x, h[4], l[4]); split1(v1.y, h[5], l[5]);
        split1(v1.z, h[6], l[6]); split1(v1.w, h[7], l[7]);
        uint32_t off = swz(r, q);
        *(uint4*)(sm + SAH + off) = make_uint4(pack2(h[0], h[1]), pack2(h[2], h[3]),
                                               pack2(h[4], h[5]), pack2(h[6], h[7]));
        *(uint4*)(sm + SAL + off) = make_uint4(pack2(l[0], l[1]), pack2(l[2], l[3]),
                                               pack2(l[4], l[5]), pack2(l[6], l[7]));
    }
}

// ---- muproj, N-split: blockIdx even/odd -> column half ----
__global__ void __launch_bounds__(NTH, 2) muproj_split_kernel(
    const float* __restrict__ mu,
    const __nv_bfloat16* __restrict__ imgT1, const __nv_bfloat16* __restrict__ imgT2,
    const __nv_bfloat16* __restrict__ imgT3,
    float* __restrict__ M1, float* __restrict__ M2, float* __restrict__ M3, int N) {
    extern __shared__ char sm[];
    int tid = threadIdx.x, wid = tid >> 5, lane = tid & 31;
    int warpM = wid >> 1, warpN = wid & 1;
    int b = blockIdx.x;
    int half = b & 1;
    int n0 = (b >> 1) * TILE;
    int h0 = half * 64;
    uint32_t sb = smem_u32(sm);
    int r0 = warpM * 32 + (lane >> 2);
    int c0b = h0 + warpN * 32 + (lane & 3) * 2;

    const __nv_bfloat16* imgs[3] = {imgT1, imgT2, imgT3};
    float* Ms[3] = {M1, M2, M3};

    for (int c = 0; c < 3; ++c) {
        __syncthreads();   // prior gemm A reads done
        for (int i = tid; i < TILE * FDIM; i += NTH) {
            uint32_t r = (uint32_t)(i >> 7), f = (uint32_t)(i & 127);
            float v = 0.f;
            if (n0 + (int)r < N) v = __ldg(mu + ((size_t)(n0 + r) * FDIM + f) * 3 + c);
            unsigned short h, l;
            split1(v, h, l);
            uint32_t off = swz(r, f >> 3) + (f & 7u) * 2u;
            *(unsigned short*)(sm + SAH + off) = h;
            *(unsigned short*)(sm + SAL + off) = l;
        }
        for (int w = 0; w < 3; ++w) {
            __syncthreads();             // A visible; prior gemm B reads done
            prefetch_B_half(sb, imgs[w], h0);
            cpa_wait<0>();
            __syncthreads();             // B visible
            float acc[2][4][4];
            zero_acc_h(acc);
            gemm3_half(sb, warpM, warpN, lane, acc);
            float* dst = Ms[w] + (size_t)c * PLANE;
#pragma unroll
            for (int mt = 0; mt < 2; ++mt)
#pragma unroll
                for (int hrow = 0; hrow < 2; ++hrow) {
                    int n = n0 + r0 + mt * 16 + hrow * 8;
                    if (n < N) {
#pragma unroll
                        for (int nidx = 0; nidx < 4; ++nidx) {
                            int cc = c0b + nidx * 8;
                            *(float2*)(dst + (size_t)n * FDIM + cc) = make_float2(
                                acc[mt][nidx][hrow * 2 + 0], acc[mt][nidx][hrow * 2 + 1]);
                        }
                    }
                }
        }
    }
}

// ---- vproj, N-split ----
__global__ void __launch_bounds__(NTH, 2) vproj_split_kernel(
    const float* __restrict__ mv, const __nv_bfloat16* __restrict__ imgV,
    float* __restrict__ out, int N) {
    extern __shared__ char sm[];
    int tid = threadIdx.x, wid = tid >> 5, lane = tid & 31;
    int warpM = wid >> 1, warpN = wid & 1;
    int b = blockIdx.x;
    int half = b & 1;
    int n0 = (b >> 1) * TILE;
    int h0 = half * 64;
    uint32_t sb = smem_u32(sm);
    int r0 = warpM * 32 + (lane >> 2);
    int c0b = h0 + warpN * 32 + (lane & 3) * 2;

    prefetch_B_half(sb, imgV, h0);
#pragma unroll 1
    for (int c = 0; c < 3; ++c) {
        __syncthreads();   // prior gemm A reads done
        load_split_A_swz(sm, mv + (size_t)c * PLANE, n0, N);
        cpa_wait<0>();     // B landed (first pass only; no-op after)
        __syncthreads();
        float acc[2][4][4];
        zero_acc_h(acc);
        gemm3_half(sb, warpM, warpN, lane, acc);
#pragma unroll
        for (int mt = 0; mt < 2; ++mt)
#pragma unroll
            for (int hrow = 0; hrow < 2; ++hrow) {
                int n = n0 + r0 + mt * 16 + hrow * 8;
                if (n < N) {
                    float* o = out + (size_t)n * FDIM * 3 + c;
#pragma unroll
                    for (int nidx = 0; nidx < 4; ++nidx) {
                        int a = c0b + nidx * 8;
                        o[(size_t)a * 3]       = acc[mt][nidx][hrow * 2 + 0];
                        o[(size_t)(a + 1) * 3] = acc[mt][nidx][hrow * 2 + 1];
                    }
                }
            }
    }
}

// ================= prep =================
struct WPtrs { const float* p[8]; };
__global__ void prep_weights(WPtrs wp) {
    int w = blockIdx.x;
    const float* src = wp.p[w];
    __nv_bfloat16* hi = g_Wimg[w];
    __nv_bfloat16* lo = g_Wimg[w] + 16384;
    for (int i = threadIdx.x; i < 16384; i += blockDim.x) {
        int k = i >> 7, g = i & 127;
        unsigned short h, l;
        split1(src[i], h, l);
        hi[g * 128 + k] = *(__nv_bfloat16*)&h;
        lo[g * 128 + k] = *(__nv_bfloat16*)&l;
    }
}

// ================= combine (DRAM-roofline) =================
__global__ void __launch_bounds__(FDIM) combine_kernel(
    const float* __restrict__ T0, const float* __restrict__ T1,
    const float* __restrict__ T2, const float* __restrict__ T3,
    const float* __restrict__ M0, const float* __restrict__ M1,
    const float* __restrict__ M2, const float* __restrict__ M3,
    float* __restrict__ ms, float* __restrict__ mv, int N) {
    int n = blockIdx.x;
    __shared__ float st[40];
    int tid = threadIdx.x;
    if (tid == 0) st[0] = T0[n];
    if (tid < 3) st[1 + tid] = T1[(size_t)n * 3 + tid];
    if (tid >= 32 && tid < 41) st[4 + tid - 32] = T2[(size_t)n * 9 + (tid - 32)];
    if (tid >= 64 && tid < 91) st[13 + tid - 64] = T3[(size_t)n * 27 + (tid - 64)];
    __syncthreads();

    float t0 = st[0];
    float t1[3], t2[9], t3[27];
#pragma unroll
    for (int k = 0; k < 3; ++k) t1[k] = st[1 + k];
#pragma unroll
    for (int k = 0; k < 9; ++k) t2[k] = st[4 + k];
#pragma unroll
    for (int k = 0; k < 27; ++k) t3[k] = st[13 + k];

    size_t base = (size_t)n * FDIM + tid;
    float m0 = M0[base];
    float m1[3], m2[3], m3[3];
#pragma unroll
    for (int c = 0; c < 3; ++c) {
        m1[c] = M1[base + (size_t)c * PLANE];
        m2[c] = M2[base + (size_t)c * PLANE];
        m3[c] = M3[base + (size_t)c * PLANE];
    }

    float s = t0 * m0;
#pragma unroll
    for (int i = 0; i < 3; ++i) s += m1[i] * t1[i];
#pragma unroll
    for (int i = 0; i < 3; ++i)
#pragma unroll
        for (int j = 0; j < 3; ++j) s += m2[i] * m2[j] * t2[i * 3 + j];
#pragma unroll
    for (int i = 0; i < 3; ++i) {
        float mi = m3[i];
#pragma unroll
        for (int j = 0; j < 3; ++j) {
            float mij = mi * m3[j];
#pragma unroll
            for (int k = 0; k < 3; ++k) s += mij * m3[k] * t3[i * 9 + j * 3 + k];
        }
    }
    ms[base] = s;

#pragma unroll
    for (int i = 0; i < 3; ++i) {
        float v = t1[i] * m0;
#pragma unroll
        for (int j = 0; j < 3; ++j) v += t2[i * 3 + j] * m1[j];
#pragma unroll
        for (int j = 0; j < 3; ++j)
#pragma unroll
            for (int k = 0; k < 3; ++k) v += t3[i * 9 + j * 3 + k] * m2[j] * m2[k];
        mv[base + (size_t)i * PLANE] = v;
    }
}

// ================= launch =================
extern "C" void kernel_launch(void* const* d_in, const int* in_sizes, int n_in,
                              void* d_out, int out_size) {
    const float* feat = (const float*)d_in[0];
    const float* mu   = (const float*)d_in[1];
    const float* T0   = (const float*)d_in[2];
    const float* T1   = (const float*)d_in[3];
    const float* T2   = (const float*)d_in[4];
    const float* T3   = (const float*)d_in[5];
    const float* Wq1  = (const float*)d_in[6];
    const float* bq1  = (const float*)d_in[7];
    const float* Wq2  = (const float*)d_in[8];
    const float* bq2  = (const float*)d_in[9];
    const float* WT1  = (const float*)d_in[10];
    const float* WT2  = (const float*)d_in[11];
    const float* WT3  = (const float*)d_in[12];
    const float* Ws1  = (const float*)d_in[13];
    const float* bs1  = (const float*)d_in[14];
    const float* Ws2  = (const float*)d_in[15];
    const float* bs2  = (const float*)d_in[16];
    const float* Wv   = (const float*)d_in[17];

    int N = in_sizes[0] / FDIM;
    if (N > MAXN) N = MAXN;

    float* out = (float*)d_out;
    float* ms_out = out;
    float* mv_out = out + (size_t)N * FDIM;

    cudaFuncSetAttribute(dense2_mma_kernel, cudaFuncAttributeMaxDynamicSharedMemorySize, (int)SMSZ6);
    cudaFuncSetAttribute(muproj_split_kernel, cudaFuncAttributeMaxDynamicSharedMemorySize, SMSZH);
    cudaFuncSetAttribute(vproj_split_kernel,  cudaFuncAttributeMaxDynamicSharedMemorySize, SMSZH);

    float *pM0, *pM1, *pM2, *pM3, *pms, *pmv;
    __nv_bfloat16* pW;
    cudaGetSymbolAddress((void**)&pM0, g_M0);
    cudaGetSymbolAddress((void**)&pM1, g_M1);
    cudaGetSymbolAddress((void**)&pM2, g_M2);
    cudaGetSymbolAddress((void**)&pM3, g_M3);
    cudaGetSymbolAddress((void**)&pms, g_ms);
    cudaGetSymbolAddress((void**)&pmv, g_mv);
    cudaGetSymbolAddress((void**)&pW,  g_Wimg);

    WPtrs wp;
    wp.p[0] = Wq1; wp.p[1] = Wq2; wp.p[2] = WT1; wp.p[3] = WT2;
    wp.p[4] = WT3; wp.p[5] = Ws1; wp.p[6] = Ws2; wp.p[7] = Wv;
    prep_weights<<<8, 256>>>(wp);

    int nb = (N + TILE - 1) / TILE;
    dense2_mma_kernel<<<nb, NTH, SMSZ6>>>(feat, pW + 0 * 32768, bq1, pW + 1 * 32768, bq2, pM0, N);
    muproj_split_kernel<<<2 * nb, NTH, SMSZH>>>(mu, pW + 2 * 32768, pW + 3 * 32768, pW + 4 * 32768,
                                                pM1, pM2, pM3, N);
    combine_kernel<<<N, FDIM>>>(T0, T1, T2, T3, pM0, pM1, pM2, pM3, pms, pmv, N);
    dense2_mma_kernel<<<nb, NTH, SMSZ6>>>(pms, pW + 5 * 32768, bs1, pW + 6 * 32768, bs2, ms_out, N);
    vproj_split_kernel<<<2 * nb, NTH, SMSZH>>>(pmv, pW + 7 * 32768, mv_out, N);
}

// round 14
// speedup vs baseline: 1.3664x; 1.0140x over previous
#include <cuda_runtime.h>
#include <cuda_bf16.h>
#include <cstdint>
#include <math.h>

#define MAXN 50000
#define FDIM 128
#define TILE 128
#define NTH  256
#define PLANE ((size_t)MAXN * FDIM)

// XOR-swizzled layout (256B rows), 96 KB, 2 CTA/SM for ALL gemm kernels
#define SAH 0u
#define SAL 32768u
#define SBH 65536u
#define SBL 81920u
#define SMSZH 98304

// -------- scratch --------
__device__ float g_M0[MAXN * FDIM];
__device__ float g_M1[3][MAXN * FDIM];
__device__ float g_M2[3][MAXN * FDIM];
__device__ float g_M3[3][MAXN * FDIM];
__device__ float g_ms[MAXN * FDIM];
__device__ float g_mv[3][MAXN * FDIM];
__device__ float g_tmp[MAXN * FDIM];         // dense2 stage-1 output
__device__ __nv_bfloat16 g_Wimg[8][32768];   // [hi 16384 | lo 16384], [out][in]

// ================= helpers =================
__device__ __forceinline__ uint32_t smem_u32(const void* p) {
    uint32_t a;
    asm("{ .reg .u64 t; cvta.to.shared.u64 t, %1; cvt.u32.u64 %0, t; }" : "=r"(a) : "l"(p));
    return a;
}
__device__ __forceinline__ uint32_t swz(uint32_t r, uint32_t q) {   // 256B rows, 16B chunks
    return (r << 8) + ((q ^ (r & 7u)) << 4);
}
__device__ __forceinline__ void cpa16(uint32_t dst, const void* src) {
    asm volatile("cp.async.cg.shared.global [%0], [%1], 16;" :: "r"(dst), "l"(src));
}
__device__ __forceinline__ void cpa_commit() { asm volatile("cp.async.commit_group;"); }
template <int K> __device__ __forceinline__ void cpa_wait() {
    asm volatile("cp.async.wait_group %0;" :: "n"(K));
}
__device__ __forceinline__ void ldm4(uint32_t* r, uint32_t addr) {
    asm volatile("ldmatrix.sync.aligned.m8n8.x4.shared.b16 {%0,%1,%2,%3}, [%4];"
                 : "=r"(r[0]), "=r"(r[1]), "=r"(r[2]), "=r"(r[3]) : "r"(addr));
}
__device__ __forceinline__ void mma16816(float* c, const uint32_t* a, uint32_t b0, uint32_t b1) {
    asm volatile(
        "mma.sync.aligned.m16n8k16.row.col.f32.bf16.bf16.f32 "
        "{%0,%1,%2,%3}, {%4,%5,%6,%7}, {%8,%9}, {%0,%1,%2,%3};"
        : "+f"(c[0]), "+f"(c[1]), "+f"(c[2]), "+f"(c[3])
        : "r"(a[0]), "r"(a[1]), "r"(a[2]), "r"(a[3]), "r"(b0), "r"(b1));
}
__device__ __forceinline__ void split1(float x, unsigned short& h, unsigned short& l) {
    __nv_bfloat16 hb = __float2bfloat16(x);
    float r = x - __bfloat162float(hb);
    __nv_bfloat16 lb = __float2bfloat16(r);
    h = *(unsigned short*)&hb;
    l = *(unsigned short*)&lb;
}
__device__ __forceinline__ uint32_t pack2(unsigned short a, unsigned short b) {
    return (uint32_t)a | ((uint32_t)b << 16);
}
__device__ __forceinline__ float sigf(float x) { return 1.f / (1.f + __expf(-x)); }

// async copy of one HALF weight image (64 out-rows, hi+lo) into swizzled B planes
__device__ __forceinline__ void prefetch_B_half(uint32_t sb, const __nv_bfloat16* __restrict__ img,
                                                int h0) {
    for (int i = threadIdx.x; i < 2048; i += NTH) {
        int half = i >> 10, idx = i & 1023;
        uint32_t r = (uint32_t)(idx >> 4), q = (uint32_t)(idx & 15);
        const uint4* src = (const uint4*)(img + half * 16384 + (size_t)(h0 + r) * 128) + q;
        uint32_t dst = sb + (half ? SBL : SBH) + swz(r, q);
        cpa16(dst, src);
    }
    cpa_commit();
}
// load fp32 [128][128] from gmem, split into swizzled A planes
__device__ __forceinline__ void load_split_A_swz(char* sm, const float* __restrict__ src,
                                                 int n0, int N) {
    for (int i = threadIdx.x; i < TILE * 16; i += NTH) {
        uint32_t r = (uint32_t)(i >> 4), q = (uint32_t)(i & 15);
        float4 v0 = make_float4(0.f, 0.f, 0.f, 0.f), v1 = v0;
        if (n0 + (int)r < N) {
            const float* p = src + (size_t)(n0 + r) * FDIM + q * 8;
            v0 = *(const float4*)p;
            v1 = *(const float4*)(p + 4);
        }
        unsigned short h[8], l[8];
        split1(v0.x, h[0], l[0]); split1(v0.y, h[1], l[1]);
        split1(v0.z, h[2], l[2]); split1(v0.w, h[3], l[3]);
        split1(v1.x, h[4], l[4]); split1(v1.y, h[5], l[5]);
        split1(v1.z, h[6], l[6]); split1(v1.w, h[7], l[7]);
        uint32_t off = swz(r, q);
        *(uint4*)(sm + SAH + off) = make_uint4(pack2(h[0], h[1]), pack2(h[2], h[3]),
                                               pack2(h[4], h[5]), pack2(h[6], h[7]));
        *(uint4*)(sm + SAL + off) = make_uint4(pack2(l[0], l[1]), pack2(l[2], l[3]),
                                               pack2(l[4], l[5]), pack2(l[6], l[7]));
    }
}

// ---- 3-term split GEMM, N=64 half: 8 warps, grid 4(M)x2(N), warp tile 32x32 ----
__device__ __forceinline__ void gemm3_half(uint32_t sb, int warpM, int warpN, int lane,
                                           float acc[2][4][4]) {
    uint32_t arow = (uint32_t)(warpM * 32 + (lane & 15));
    uint32_t brow = (uint32_t)(warpN * 32 + (lane & 15));
    uint32_t qb = (uint32_t)(lane >> 4);
#pragma unroll
    for (int kc = 0; kc < 8; ++kc) {
        uint32_t q = (uint32_t)(kc * 2) + qb;
        uint32_t ah[2][4], al[2][4], bh[2][4], bl[2][4];
#pragma unroll
        for (int mt = 0; mt < 2; ++mt) {
            uint32_t off = swz(arow + (uint32_t)(mt * 16), q);
            ldm4(ah[mt], sb + SAH + off);
            ldm4(al[mt], sb + SAL + off);
        }
#pragma unroll
        for (int nt = 0; nt < 2; ++nt) {
            uint32_t off = swz(brow + (uint32_t)(nt * 16), q);
            ldm4(bh[nt], sb + SBH + off);
            ldm4(bl[nt], sb + SBL + off);
        }
#pragma unroll
        for (int mt = 0; mt < 2; ++mt)
#pragma unroll
            for (int nt = 0; nt < 2; ++nt) {
                mma16816(acc[mt][nt * 2 + 0], ah[mt], bh[nt][0], bh[nt][2]);
                mma16816(acc[mt][nt * 2 + 1], ah[mt], bh[nt][1], bh[nt][3]);
                mma16816(acc[mt][nt * 2 + 0], ah[mt], bl[nt][0], bl[nt][2]);
                mma16816(acc[mt][nt * 2 + 1], ah[mt], bl[nt][1], bl[nt][3]);
                mma16816(acc[mt][nt * 2 + 0], al[mt], bh[nt][0], bh[nt][2]);
                mma16816(acc[mt][nt * 2 + 1], al[mt], bh[nt][1], bh[nt][3]);
            }
    }
}
__device__ __forceinline__ void zero_acc_h(float acc[2][4][4]) {
#pragma unroll
    for (int m = 0; m < 2; ++m)
#pragma unroll
        for (int n = 0; n < 4; ++n)
#pragma unroll
            for (int j = 0; j < 4; ++j) acc[m][n][j] = 0.f;
}

// ================= dense2 stage 1: silu(in @ W1 + b1) -> fp32 scratch (N-split) =================
__global__ void __launch_bounds__(NTH, 2) dense1_kernel(
    const float* __restrict__ in, const __nv_bfloat16* __restrict__ img,
    const float* __restrict__ bias, float* __restrict__ out, int N) {
    extern __shared__ char sm[];
    int tid = threadIdx.x, wid = tid >> 5, lane = tid & 31;
    int warpM = wid >> 1, warpN = wid & 1;
    int b = blockIdx.x;
    int half = b & 1;
    int n0 = (b >> 1) * TILE;
    int h0 = half * 64;
    uint32_t sb = smem_u32(sm);
    int r0 = warpM * 32 + (lane >> 2);
    int c0b = h0 + warpN * 32 + (lane & 3) * 2;

    prefetch_B_half(sb, img, h0);
    load_split_A_swz(sm, in, n0, N);   // overlaps with B prefetch
    cpa_wait<0>();
    __syncthreads();

    float acc[2][4][4];
    zero_acc_h(acc);
    gemm3_half(sb, warpM, warpN, lane, acc);

#pragma unroll
    for (int mt = 0; mt < 2; ++mt)
#pragma unroll
        for (int hrow = 0; hrow < 2; ++hrow) {
            int n = n0 + r0 + mt * 16 + hrow * 8;
            if (n < N) {
#pragma unroll
                for (int nidx = 0; nidx < 4; ++nidx) {
                    int c = c0b + nidx * 8;
                    float2 bb = *(const float2*)(bias + c);
                    float x = acc[mt][nidx][hrow * 2 + 0] + bb.x;
                    float y = acc[mt][nidx][hrow * 2 + 1] + bb.y;
                    *(float2*)(out + (size_t)n * FDIM + c) =
                        make_float2(x * sigf(x), y * sigf(y));
                }
            }
        }
}

// ================= dense2 stage 2: in @ W2 + b2 -> out (N-split) =================
__global__ void __launch_bounds__(NTH, 2) dense2b_kernel(
    const float* __restrict__ in, const __nv_bfloat16* __restrict__ img,
    const float* __restrict__ bias, float* __restrict__ out, int N) {
    extern __shared__ char sm[];
    int tid = threadIdx.x, wid = tid >> 5, lane = tid & 31;
    int warpM = wid >> 1, warpN = wid & 1;
    int b = blockIdx.x;
    int half = b & 1;
    int n0 = (b >> 1) * TILE;
    int h0 = half * 64;
    uint32_t sb = smem_u32(sm);
    int r0 = warpM * 32 + (lane >> 2);
    int c0b = h0 + warpN * 32 + (lane & 3) * 2;

    prefetch_B_half(sb, img, h0);
    load_split_A_swz(sm, in, n0, N);
    cpa_wait<0>();
    __syncthreads();

    float acc[2][4][4];
    zero_acc_h(acc);
    gemm3_half(sb, warpM, warpN, lane, acc);

#pragma unroll
    for (int mt = 0; mt < 2; ++mt)
#pragma unroll
        for (int hrow = 0; hrow < 2; ++hrow) {
            int n = n0 + r0 + mt * 16 + hrow * 8;
            if (n < N) {
#pragma unroll
                for (int nidx = 0; nidx < 4; ++nidx) {
                    int c = c0b + nidx * 8;
                    float2 bb = *(const float2*)(bias + c);
                    *(float2*)(out + (size_t)n * FDIM + c) = make_float2(
                        acc[mt][nidx][hrow * 2 + 0] + bb.x,
                        acc[mt][nidx][hrow * 2 + 1] + bb.y);
                }
            }
        }
}

// ================= muproj, N-split, hoisted B prefetch =================
__global__ void __launch_bounds__(NTH, 2) muproj_split_kernel(
    const float* __restrict__ mu,
    const __nv_bfloat16* __restrict__ imgT1, const __nv_bfloat16* __restrict__ imgT2,
    const __nv_bfloat16* __restrict__ imgT3,
    float* __restrict__ M1, float* __restrict__ M2, float* __restrict__ M3, int N) {
    extern __shared__ char sm[];
    int tid = threadIdx.x, wid = tid >> 5, lane = tid & 31;
    int warpM = wid >> 1, warpN = wid & 1;
    int b = blockIdx.x;
    int half = b & 1;
    int n0 = (b >> 1) * TILE;
    int h0 = half * 64;
    uint32_t sb = smem_u32(sm);
    int r0 = warpM * 32 + (lane >> 2);
    int c0b = h0 + warpN * 32 + (lane & 3) * 2;

    const __nv_bfloat16* imgs[3] = {imgT1, imgT2, imgT3};
    float* Ms[3] = {M1, M2, M3};

    prefetch_B_half(sb, imgs[0], h0);    // first B in flight
    int it = 0;
    for (int c = 0; c < 3; ++c) {
        // gather plane c of mu (overlaps pending B prefetch). Safe vs prior gemm:
        // post-gemm barrier below ran before we get here.
        for (int i = tid; i < TILE * FDIM; i += NTH) {
            uint32_t r = (uint32_t)(i >> 7), f = (uint32_t)(i & 127);
            float v = 0.f;
            if (n0 + (int)r < N) v = __ldg(mu + ((size_t)(n0 + r) * FDIM + f) * 3 + c);
            unsigned short h, l;
            split1(v, h, l);
            uint32_t off = swz(r, f >> 3) + (f & 7u) * 2u;
            *(unsigned short*)(sm + SAH + off) = h;
            *(unsigned short*)(sm + SAL + off) = l;
        }
        for (int w = 0; w < 3; ++w, ++it) {
            cpa_wait<0>();               // current B landed (usually already done)
            __syncthreads();             // B + A visible block-wide
            float acc[2][4][4];
            zero_acc_h(acc);
            gemm3_half(sb, warpM, warpN, lane, acc);
            __syncthreads();             // all B (and A) reads done
            if (it < 8)                  // launch next B; overlaps the stores below
                prefetch_B_half(sb, imgs[(w + 1) % 3], h0);
            float* dst = Ms[w] + (size_t)c * PLANE;
#pragma unroll
            for (int mt = 0; mt < 2; ++mt)
#pragma unroll
                for (int hrow = 0; hrow < 2; ++hrow) {
                    int n = n0 + r0 + mt * 16 + hrow * 8;
                    if (n < N) {
#pragma unroll
                        for (int nidx = 0; nidx < 4; ++nidx) {
                            int cc = c0b + nidx * 8;
                            *(float2*)(dst + (size_t)n * FDIM + cc) = make_float2(
                                acc[mt][nidx][hrow * 2 + 0], acc[mt][nidx][hrow * 2 + 1]);
                        }
                    }
                }
        }
    }
}

// ================= vproj, N-split =================
__global__ void __launch_bounds__(NTH, 2) vproj_split_kernel(
    const float* __restrict__ mv, const __nv_bfloat16* __restrict__ imgV,
    float* __restrict__ out, int N) {
    extern __shared__ char sm[];
    int tid = threadIdx.x, wid = tid >> 5, lane = tid & 31;
    int warpM = wid >> 1, warpN = wid & 1;
    int b = blockIdx.x;
    int half = b & 1;
    int n0 = (b >> 1) * TILE;
    int h0 = half * 64;
    uint32_t sb = smem_u32(sm);
    int r0 = warpM * 32 + (lane >> 2);
    int c0b = h0 + warpN * 32 + (lane & 3) * 2;

    prefetch_B_half(sb, imgV, h0);
#pragma unroll 1
    for (int c = 0; c < 3; ++c) {
        load_split_A_swz(sm, mv + (size_t)c * PLANE, n0, N);   // overlaps B (c==0)
        cpa_wait<0>();
        __syncthreads();
        float acc[2][4][4];
        zero_acc_h(acc);
        gemm3_half(sb, warpM, warpN, lane, acc);
        __syncthreads();   // A reads done before next overwrite
#pragma unroll
        for (int mt = 0; mt < 2; ++mt)
#pragma unroll
            for (int hrow = 0; hrow < 2; ++hrow) {
                int n = n0 + r0 + mt * 16 + hrow * 8;
                if (n < N) {
                    float* o = out + (size_t)n * FDIM * 3 + c;
#pragma unroll
                    for (int nidx = 0; nidx < 4; ++nidx) {
                        int a = c0b + nidx * 8;
                        o[(size_t)a * 3]       = acc[mt][nidx][hrow * 2 + 0];
                        o[(size_t)(a + 1) * 3] = acc[mt][nidx][hrow * 2 + 1];
                    }
                }
            }
    }
}

// ================= prep =================
struct WPtrs { const float* p[8]; };
__global__ void prep_weights(WPtrs wp) {
    int w = blockIdx.x;
    const float* src = wp.p[w];
    __nv_bfloat16* hi = g_Wimg[w];
    __nv_bfloat16* lo = g_Wimg[w] + 16384;
    for (int i = threadIdx.x; i < 16384; i += blockDim.x) {
        int k = i >> 7, g = i & 127;
        unsigned short h, l;
        split1(src[i], h, l);
        hi[g * 128 + k] = *(__nv_bfloat16*)&h;
        lo[g * 128 + k] = *(__nv_bfloat16*)&l;
    }
}

// ================= combine (DRAM-roofline) =================
__global__ void __launch_bounds__(FDIM) combine_kernel(
    const float* __restrict__ T0, const float* __restrict__ T1,
    const float* __restrict__ T2, const float* __restrict__ T3,
    const float* __restrict__ M0, const float* __restrict__ M1,
    const float* __restrict__ M2, const float* __restrict__ M3,
    float* __restrict__ ms, float* __restrict__ mv, int N) {
    int n = blockIdx.x;
    __shared__ float st[40];
    int tid = threadIdx.x;
    if (tid == 0) st[0] = T0[n];
    if (tid < 3) st[1 + tid] = T1[(size_t)n * 3 + tid];
    if (tid >= 32 && tid < 41) st[4 + tid - 32] = T2[(size_t)n * 9 + (tid - 32)];
    if (tid >= 64 && tid < 91) st[13 + tid - 64] = T3[(size_t)n * 27 + (tid - 64)];
    __syncthreads();

    float t0 = st[0];
    float t1[3], t2[9], t3[27];
#pragma unroll
    for (int k = 0; k < 3; ++k) t1[k] = st[1 + k];
#pragma unroll
    for (int k = 0; k < 9; ++k) t2[k] = st[4 + k];
#pragma unroll
    for (int k = 0; k < 27; ++k) t3[k] = st[13 + k];

    size_t base = (size_t)n * FDIM + tid;
    float m0 = M0[base];
    float m1[3], m2[3], m3[3];
#pragma unroll
    for (int c = 0; c < 3; ++c) {
        m1[c] = M1[base + (size_t)c * PLANE];
        m2[c] = M2[base + (size_t)c * PLANE];
        m3[c] = M3[base + (size_t)c * PLANE];
    }

    float s = t0 * m0;
#pragma unroll
    for (int i = 0; i < 3; ++i) s += m1[i] * t1[i];
#pragma unroll
    for (int i = 0; i < 3; ++i)
#pragma unroll
        for (int j = 0; j < 3; ++j) s += m2[i] * m2[j] * t2[i * 3 + j];
#pragma unroll
    for (int i = 0; i < 3; ++i) {
        float mi = m3[i];
#pragma unroll
        for (int j = 0; j < 3; ++j) {
            float mij = mi * m3[j];
#pragma unroll
            for (int k = 0; k < 3; ++k) s += mij * m3[k] * t3[i * 9 + j * 3 + k];
        }
    }
    ms[base] = s;

#pragma unroll
    for (int i = 0; i < 3; ++i) {
        float v = t1[i] * m0;
#pragma unroll
        for (int j = 0; j < 3; ++j) v += t2[i * 3 + j] * m1[j];
#pragma unroll
        for (int j = 0; j < 3; ++j)
#pragma unroll
            for (int k = 0; k < 3; ++k) v += t3[i * 9 + j * 3 + k] * m2[j] * m2[k];
        mv[base + (size_t)i * PLANE] = v;
    }
}

// ================= launch =================
extern "C" void kernel_launch(void* const* d_in, const int* in_sizes, int n_in,
                              void* d_out, int out_size) {
    const float* feat = (const float*)d_in[0];
    const float* mu   = (const float*)d_in[1];
    const float* T0   = (const float*)d_in[2];
    const float* T1   = (const float*)d_in[3];
    const float* T2   = (const float*)d_in[4];
    const float* T3   = (const float*)d_in[5];
    const float* Wq1  = (const float*)d_in[6];
    const float* bq1  = (const float*)d_in[7];
    const float* Wq2  = (const float*)d_in[8];
    const float* bq2  = (const float*)d_in[9];
    const float* WT1  = (const float*)d_in[10];
    const float* WT2  = (const float*)d_in[11];
    const float* WT3  = (const float*)d_in[12];
    const float* Ws1  = (const float*)d_in[13];
    const float* bs1  = (const float*)d_in[14];
    const float* Ws2  = (const float*)d_in[15];
    const float* bs2  = (const float*)d_in[16];
    const float* Wv   = (const float*)d_in[17];

    int N = in_sizes[0] / FDIM;
    if (N > MAXN) N = MAXN;

    float* out = (float*)d_out;
    float* ms_out = out;
    float* mv_out = out + (size_t)N * FDIM;

    cudaFuncSetAttribute(dense1_kernel,       cudaFuncAttributeMaxDynamicSharedMemorySize, SMSZH);
    cudaFuncSetAttribute(dense2b_kernel,      cudaFuncAttributeMaxDynamicSharedMemorySize, SMSZH);
    cudaFuncSetAttribute(muproj_split_kernel, cudaFuncAttributeMaxDynamicSharedMemorySize, SMSZH);
    cudaFuncSetAttribute(vproj_split_kernel,  cudaFuncAttributeMaxDynamicSharedMemorySize, SMSZH);

    float *pM0, *pM1, *pM2, *pM3, *pms, *pmv, *ptmp;
    __nv_bfloat16* pW;
    cudaGetSymbolAddress((void**)&pM0, g_M0);
    cudaGetSymbolAddress((void**)&pM1, g_M1);
    cudaGetSymbolAddress((void**)&pM2, g_M2);
    cudaGetSymbolAddress((void**)&pM3, g_M3);
    cudaGetSymbolAddress((void**)&pms, g_ms);
    cudaGetSymbolAddress((void**)&pmv, g_mv);
    cudaGetSymbolAddress((void**)&ptmp, g_tmp);
    cudaGetSymbolAddress((void**)&pW,  g_Wimg);

    WPtrs wp;
    wp.p[0] = Wq1; wp.p[1] = Wq2; wp.p[2] = WT1; wp.p[3] = WT2;
    wp.p[4] = WT3; wp.p[5] = Ws1; wp.p[6] = Ws2; wp.p[7] = Wv;
    prep_weights<<<8, 256>>>(wp);

    int nb = (N + TILE - 1) / TILE;
    dense1_kernel<<<2 * nb, NTH, SMSZH>>>(feat, pW + 0 * 32768, bq1, ptmp, N);
    dense2b_kernel<<<2 * nb, NTH, SMSZH>>>(ptmp, pW + 1 * 32768, bq2, pM0, N);
    muproj_split_kernel<<<2 * nb, NTH, SMSZH>>>(mu, pW + 2 * 32768, pW + 3 * 32768,
                                                pW + 4 * 32768, pM1, pM2, pM3, N);
    combine_kernel<<<N, FDIM>>>(T0, T1, T2, T3, pM0, pM1, pM2, pM3, pms, pmv, N);
    dense1_kernel<<<2 * nb, NTH, SMSZH>>>(pms, pW + 5 * 32768, bs1, ptmp, N);
    dense2b_kernel<<<2 * nb, NTH, SMSZH>>>(ptmp, pW + 6 * 32768, bs2, ms_out, N);
    vproj_split_kernel<<<2 * nb, NTH, SMSZH>>>(pmv, pW + 7 * 32768, mv_out, N);
}

// round 16
// speedup vs baseline: 1.4023x; 1.0263x over previous
#include <cuda_runtime.h>
#include <cuda_bf16.h>
#include <cstdint>
#include <math.h>

#define MAXN  50000
#define MAXNP 50048
#define FDIM 128
#define TILE 128
#define NTH  256
#define PLANE  ((size_t)MAXN * FDIM)
#define PLANEP ((size_t)MAXNP * FDIM)

// XOR-swizzled layout (256B rows), 96 KB, 2 CTA/SM for all gemm kernels
#define SAH 0u
#define SAL 32768u
#define SBH 65536u
#define SBL 81920u
#define SMSZH 98304

// -------- scratch (aliased: g_bfA holds mu planes, then mv planes) --------
__device__ float g_M0[MAXN * FDIM];
__device__ float g_M1[3][MAXN * FDIM];
__device__ float g_M2[3][MAXN * FDIM];
__device__ float g_M3[3][MAXN * FDIM];
__device__ __nv_bfloat16 g_bfA[3][2][PLANEP];    // phase A: mu hi/lo; phase B: mv hi/lo
__device__ __nv_bfloat16 g_tmp[2][PLANEP];       // dense stage-1 out, pre-split
__device__ __nv_bfloat16 g_msS[2][PLANEP];       // ms, pre-split
__device__ __nv_bfloat16 g_Wimg[8][32768];       // [hi 16384 | lo 16384], [out][in]

// ================= helpers =================
__device__ __forceinline__ uint32_t smem_u32(const void* p) {
    uint32_t a;
    asm("{ .reg .u64 t; cvta.to.shared.u64 t, %1; cvt.u32.u64 %0, t; }" : "=r"(a) : "l"(p));
    return a;
}
__device__ __forceinline__ uint32_t swz(uint32_t r, uint32_t q) {
    return (r << 8) + ((q ^ (r & 7u)) << 4);
}
__device__ __forceinline__ void cpa16(uint32_t dst, const void* src) {
    asm volatile("cp.async.cg.shared.global [%0], [%1], 16;" :: "r"(dst), "l"(src));
}
__device__ __forceinline__ void cpa_commit() { asm volatile("cp.async.commit_group;"); }
template <int K> __device__ __forceinline__ void cpa_wait() {
    asm volatile("cp.async.wait_group %0;" :: "n"(K));
}
__device__ __forceinline__ void ldm4(uint32_t* r, uint32_t addr) {
    asm volatile("ldmatrix.sync.aligned.m8n8.x4.shared.b16 {%0,%1,%2,%3}, [%4];"
                 : "=r"(r[0]), "=r"(r[1]), "=r"(r[2]), "=r"(r[3]) : "r"(addr));
}
__device__ __forceinline__ void mma16816(float* c, const uint32_t* a, uint32_t b0, uint32_t b1) {
    asm volatile(
        "mma.sync.aligned.m16n8k16.row.col.f32.bf16.bf16.f32 "
        "{%0,%1,%2,%3}, {%4,%5,%6,%7}, {%8,%9}, {%0,%1,%2,%3};"
        : "+f"(c[0]), "+f"(c[1]), "+f"(c[2]), "+f"(c[3])
        : "r"(a[0]), "r"(a[1]), "r"(a[2]), "r"(a[3]), "r"(b0), "r"(b1));
}
__device__ __forceinline__ void split1(float x, unsigned short& h, unsigned short& l) {
    __nv_bfloat16 hb = __float2bfloat16(x);
    float r = x - __bfloat162float(hb);
    __nv_bfloat16 lb = __float2bfloat16(r);
    h = *(unsigned short*)&hb;
    l = *(unsigned short*)&lb;
}
__device__ __forceinline__ uint32_t pack2(unsigned short a, unsigned short b) {
    return (uint32_t)a | ((uint32_t)b << 16);
}
__device__ __forceinline__ float sigf(float x) { return 1.f / (1.f + __expf(-x)); }

// async copy of one HALF weight image (64 out-rows, hi+lo) into swizzled B planes
__device__ __forceinline__ void prefetch_B_half(uint32_t sb, const __nv_bfloat16* __restrict__ img,
                                                int h0) {
    for (int i = threadIdx.x; i < 2048; i += NTH) {
        int half = i >> 10, idx = i & 1023;
        uint32_t r = (uint32_t)(idx >> 4), q = (uint32_t)(idx & 15);
        const uint4* src = (const uint4*)(img + half * 16384 + (size_t)(h0 + r) * 128) + q;
        uint32_t dst = sb + (half ? SBL : SBH) + swz(r, q);
        cpa16(dst, src);
    }
    cpa_commit();
}
// async copy of a pre-split A tile (hi+lo planes) into swizzled A planes
__device__ __forceinline__ void prefetch_A_sp(uint32_t sb, const __nv_bfloat16* __restrict__ hi,
                                              const __nv_bfloat16* __restrict__ lo, int n0) {
    for (int i = threadIdx.x; i < TILE * 16; i += NTH) {
        uint32_t r = (uint32_t)(i >> 4), q = (uint32_t)(i & 15);
        uint32_t off = swz(r, q);
        cpa16(sb + SAH + off, (const uint4*)(hi + (size_t)(n0 + r) * FDIM) + q);
        cpa16(sb + SAL + off, (const uint4*)(lo + (size_t)(n0 + r) * FDIM) + q);
    }
    cpa_commit();
}
// load fp32 [128][128] from gmem (guarded), split into swizzled A planes
__device__ __forceinline__ void load_split_A_swz(char* sm, const float* __restrict__ src,
                                                 int n0, int N) {
    for (int i = threadIdx.x; i < TILE * 16; i += NTH) {
        uint32_t r = (uint32_t)(i >> 4), q = (uint32_t)(i & 15);
        float4 v0 = make_float4(0.f, 0.f, 0.f, 0.f), v1 = v0;
        if (n0 + (int)r < N) {
            const float* p = src + (size_t)(n0 + r) * FDIM + q * 8;
            v0 = *(const float4*)p;
            v1 = *(const float4*)(p + 4);
        }
        unsigned short h[8], l[8];
        split1(v0.x, h[0], l[0]); split1(v0.y, h[1], l[1]);
        split1(v0.z, h[2], l[2]); split1(v0.w, h[3], l[3]);
        split1(v1.x, h[4], l[4]); split1(v1.y, h[5], l[5]);
        split1(v1.z, h[6], l[6]); split1(v1.w, h[7], l[7]);
        uint32_t off = swz(r, q);
        *(uint4*)(sm + SAH + off) = make_uint4(pack2(h[0], h[1]), pack2(h[2], h[3]),
                                               pack2(h[4], h[5]), pack2(h[6], h[7]));
        *(uint4*)(sm + SAL + off) = make_uint4(pack2(l[0], l[1]), pack2(l[2], l[3]),
                                               pack2(l[4], l[5]), pack2(l[6], l[7]));
    }
}

// ---- 3-term split GEMM, N=64 half: 8 warps, grid 4(M)x2(N), warp tile 32x32 ----
__device__ __forceinline__ void gemm3_half(uint32_t sb, int warpM, int warpN, int lane,
                                           float acc[2][4][4]) {
    uint32_t arow = (uint32_t)(warpM * 32 + (lane & 15));
    uint32_t brow = (uint32_t)(warpN * 32 + (lane & 15));
    uint32_t qb = (uint32_t)(lane >> 4);
#pragma unroll
    for (int kc = 0; kc < 8; ++kc) {
        uint32_t q = (uint32_t)(kc * 2) + qb;
        uint32_t ah[2][4], al[2][4], bh[2][4], bl[2][4];
#pragma unroll
        for (int mt = 0; mt < 2; ++mt) {
            uint32_t off = swz(arow + (uint32_t)(mt * 16), q);
            ldm4(ah[mt], sb + SAH + off);
            ldm4(al[mt], sb + SAL + off);
        }
#pragma unroll
        for (int nt = 0; nt < 2; ++nt) {
            uint32_t off = swz(brow + (uint32_t)(nt * 16), q);
            ldm4(bh[nt], sb + SBH + off);
            ldm4(bl[nt], sb + SBL + off);
        }
#pragma unroll
        for (int mt = 0; mt < 2; ++mt)
#pragma unroll
            for (int nt = 0; nt < 2; ++nt) {
                mma16816(acc[mt][nt * 2 + 0], ah[mt], bh[nt][0], bh[nt][2]);
                mma16816(acc[mt][nt * 2 + 1], ah[mt], bh[nt][1], bh[nt][3]);
                mma16816(acc[mt][nt * 2 + 0], ah[mt], bl[nt][0], bl[nt][2]);
                mma16816(acc[mt][nt * 2 + 1], ah[mt], bl[nt][1], bl[nt][3]);
                mma16816(acc[mt][nt * 2 + 0], al[mt], bh[nt][0], bh[nt][2]);
                mma16816(acc[mt][nt * 2 + 1], al[mt], bh[nt][1], bh[nt][3]);
            }
    }
}
__device__ __forceinline__ void zero_acc_h(float acc[2][4][4]) {
#pragma unroll
    for (int m = 0; m < 2; ++m)
#pragma unroll
        for (int n = 0; n < 4; ++n)
#pragma unroll
            for (int j = 0; j < 4; ++j) acc[m][n][j] = 0.f;
}

// ================= prep kernels =================
struct WPtrs { const float* p[8]; };
__global__ void prep_weights(WPtrs wp) {
    int w = blockIdx.x;
    const float* src = wp.p[w];
    __nv_bfloat16* hi = g_Wimg[w];
    __nv_bfloat16* lo = g_Wimg[w] + 16384;
    for (int i = threadIdx.x; i < 16384; i += blockDim.x) {
        int k = i >> 7, g = i & 127;
        unsigned short h, l;
        split1(src[i], h, l);
        hi[g * 128 + k] = *(__nv_bfloat16*)&h;
        lo[g * 128 + k] = *(__nv_bfloat16*)&l;
    }
}
// de-interleave + split mu -> 3 hi/lo bf16 planes (flat coalesced reads)
__global__ void mu_split_kernel(const float* __restrict__ mu, int N) {
    size_t total = (size_t)N * FDIM * 3;
    for (size_t i = (size_t)blockIdx.x * blockDim.x + threadIdx.x; i < total;
         i += (size_t)gridDim.x * blockDim.x) {
        float v = __ldg(mu + i);
        int c = (int)(i % 3);
        size_t nf = i / 3;
        unsigned short h, l;
        split1(v, h, l);
        g_bfA[c][0][nf] = *(__nv_bfloat16*)&h;
        g_bfA[c][1][nf] = *(__nv_bfloat16*)&l;
    }
}

// ================= dense stage 1 (fp32 A, split out) =================
__global__ void __launch_bounds__(NTH, 2) dense1_feat_kernel(
    const float* __restrict__ in, const __nv_bfloat16* __restrict__ img,
    const float* __restrict__ bias, int N) {
    extern __shared__ char sm[];
    int tid = threadIdx.x, wid = tid >> 5, lane = tid & 31;
    int warpM = wid >> 1, warpN = wid & 1;
    int b = blockIdx.x;
    int half = b & 1;
    int n0 = (b >> 1) * TILE;
    int h0 = half * 64;
    uint32_t sb = smem_u32(sm);
    int r0 = warpM * 32 + (lane >> 2);
    int c0b = h0 + warpN * 32 + (lane & 3) * 2;

    prefetch_B_half(sb, img, h0);
    load_split_A_swz(sm, in, n0, N);
    cpa_wait<0>();
    __syncthreads();

    float acc[2][4][4];
    zero_acc_h(acc);
    gemm3_half(sb, warpM, warpN, lane, acc);

#pragma unroll
    for (int mt = 0; mt < 2; ++mt)
#pragma unroll
        for (int hrow = 0; hrow < 2; ++hrow) {
            int n = n0 + r0 + mt * 16 + hrow * 8;
            if (n < N) {
#pragma unroll
                for (int nidx = 0; nidx < 4; ++nidx) {
                    int c = c0b + nidx * 8;
                    float2 bb = *(const float2*)(bias + c);
                    float x = acc[mt][nidx][hrow * 2 + 0] + bb.x;
                    float y = acc[mt][nidx][hrow * 2 + 1] + bb.y;
                    x *= sigf(x); y *= sigf(y);
                    unsigned short hx, lx, hy, ly;
                    split1(x, hx, lx); split1(y, hy, ly);
                    *(uint32_t*)((unsigned short*)g_tmp[0] + (size_t)n * FDIM + c) = pack2(hx, hy);
                    *(uint32_t*)((unsigned short*)g_tmp[1] + (size_t)n * FDIM + c) = pack2(lx, ly);
                }
            }
        }
}

// ================= dense stage 1 (pre-split A, split out) =================
__global__ void __launch_bounds__(NTH, 2) dense1_sp_kernel(
    const __nv_bfloat16* __restrict__ aH, const __nv_bfloat16* __restrict__ aL,
    const __nv_bfloat16* __restrict__ img, const float* __restrict__ bias, int N) {
    extern __shared__ char sm[];
    int tid = threadIdx.x, wid = tid >> 5, lane = tid & 31;
    int warpM = wid >> 1, warpN = wid & 1;
    int b = blockIdx.x;
    int half = b & 1;
    int n0 = (b >> 1) * TILE;
    int h0 = half * 64;
    uint32_t sb = smem_u32(sm);
    int r0 = warpM * 32 + (lane >> 2);
    int c0b = h0 + warpN * 32 + (lane & 3) * 2;

    prefetch_B_half(sb, img, h0);
    prefetch_A_sp(sb, aH, aL, n0);
    cpa_wait<0>();
    __syncthreads();

    float acc[2][4][4];
    zero_acc_h(acc);
    gemm3_half(sb, warpM, warpN, lane, acc);

#pragma unroll
    for (int mt = 0; mt < 2; ++mt)
#pragma unroll
        for (int hrow = 0; hrow < 2; ++hrow) {
            int n = n0 + r0 + mt * 16 + hrow * 8;
            if (n < N) {
#pragma unroll
                for (int nidx = 0; nidx < 4; ++nidx) {
                    int c = c0b + nidx * 8;
                    float2 bb = *(const float2*)(bias + c);
                    float x = acc[mt][nidx][hrow * 2 + 0] + bb.x;
                    float y = acc[mt][nidx][hrow * 2 + 1] + bb.y;
                    x *= sigf(x); y *= sigf(y);
                    unsigned short hx, lx, hy, ly;
                    split1(x, hx, lx); split1(y, hy, ly);
                    *(uint32_t*)((unsigned short*)g_tmp[0] + (size_t)n * FDIM + c) = pack2(hx, hy);
                    *(uint32_t*)((unsigned short*)g_tmp[1] + (size_t)n * FDIM + c) = pack2(lx, ly);
                }
            }
        }
}

// ================= dense stage 2 (pre-split A, fp32 out + bias) =================
__global__ void __launch_bounds__(NTH, 2) dense2b_kernel(
    const __nv_bfloat16* __restrict__ aH, const __nv_bfloat16* __restrict__ aL,
    const __nv_bfloat16* __restrict__ img, const float* __restrict__ bias,
    float* __restrict__ out, int N) {
    extern __shared__ char sm[];
    int tid = threadIdx.x, wid = tid >> 5, lane = tid & 31;
    int warpM = wid >> 1, warpN = wid & 1;
    int b = blockIdx.x;
    int half = b & 1;
    int n0 = (b >> 1) * TILE;
    int h0 = half * 64;
    uint32_t sb = smem_u32(sm);
    int r0 = warpM * 32 + (lane >> 2);
    int c0b = h0 + warpN * 32 + (lane & 3) * 2;

    prefetch_B_half(sb, img, h0);
    prefetch_A_sp(sb, aH, aL, n0);
    cpa_wait<0>();
    __syncthreads();

    float acc[2][4][4];
    zero_acc_h(acc);
    gemm3_half(sb, warpM, warpN, lane, acc);

#pragma unroll
    for (int mt = 0; mt < 2; ++mt)
#pragma unroll
        for (int hrow = 0; hrow < 2; ++hrow) {
            int n = n0 + r0 + mt * 16 + hrow * 8;
            if (n < N) {
#pragma unroll
                for (int nidx = 0; nidx < 4; ++nidx) {
                    int c = c0b + nidx * 8;
                    float2 bb = *(const float2*)(bias + c);
                    *(float2*)(out + (size_t)n * FDIM + c) = make_float2(
                        acc[mt][nidx][hrow * 2 + 0] + bb.x,
                        acc[mt][nidx][hrow * 2 + 1] + bb.y);
                }
            }
        }
}

// ================= muproj: pre-split A, fully pipelined prefetch =================
__global__ void __launch_bounds__(NTH, 2) muproj_split_kernel(
    const __nv_bfloat16* __restrict__ imgT1, const __nv_bfloat16* __restrict__ imgT2,
    const __nv_bfloat16* __restrict__ imgT3,
    float* __restrict__ M1, float* __restrict__ M2, float* __restrict__ M3, int N) {
    extern __shared__ char sm[];
    int tid = threadIdx.x, wid = tid >> 5, lane = tid & 31;
    int warpM = wid >> 1, warpN = wid & 1;
    int b = blockIdx.x;
    int half = b & 1;
    int n0 = (b >> 1) * TILE;
    int h0 = half * 64;
    uint32_t sb = smem_u32(sm);
    int r0 = warpM * 32 + (lane >> 2);
    int c0b = h0 + warpN * 32 + (lane & 3) * 2;

    const __nv_bfloat16* imgs[3] = {imgT1, imgT2, imgT3};
    float* Ms[3] = {M1, M2, M3};

    prefetch_B_half(sb, imgs[0], h0);
    prefetch_A_sp(sb, g_bfA[0][0], g_bfA[0][1], n0);
    for (int c = 0; c < 3; ++c) {
        for (int w = 0; w < 3; ++w) {
            cpa_wait<0>();
            __syncthreads();
            float acc[2][4][4];
            zero_acc_h(acc);
            gemm3_half(sb, warpM, warpN, lane, acc);
            __syncthreads();      // all smem reads done -> safe to overwrite
            if (w < 2) {
                prefetch_B_half(sb, imgs[w + 1], h0);
            } else if (c < 2) {
                prefetch_B_half(sb, imgs[0], h0);
                prefetch_A_sp(sb, g_bfA[c + 1][0], g_bfA[c + 1][1], n0);
            }
            float* dst = Ms[w] + (size_t)c * PLANE;
#pragma unroll
            for (int mt = 0; mt < 2; ++mt)
#pragma unroll
                for (int hrow = 0; hrow < 2; ++hrow) {
                    int n = n0 + r0 + mt * 16 + hrow * 8;
                    if (n < N) {
#pragma unroll
                        for (int nidx = 0; nidx < 4; ++nidx) {
                            int cc = c0b + nidx * 8;
                            *(float2*)(dst + (size_t)n * FDIM + cc) = make_float2(
                                acc[mt][nidx][hrow * 2 + 0], acc[mt][nidx][hrow * 2 + 1]);
                        }
                    }
                }
        }
    }
}

// ================= vproj: pre-split A (g_bfA reused as mv planes) =================
__global__ void __launch_bounds__(NTH, 2) vproj_split_kernel(
    const __nv_bfloat16* __restrict__ imgV, float* __restrict__ out, int N) {
    extern __shared__ char sm[];
    int tid = threadIdx.x, wid = tid >> 5, lane = tid & 31;
    int warpM = wid >> 1, warpN = wid & 1;
    int b = blockIdx.x;
    int half = b & 1;
    int n0 = (b >> 1) * TILE;
    int h0 = half * 64;
    uint32_t sb = smem_u32(sm);
    int r0 = warpM * 32 + (lane >> 2);
    int c0b = h0 + warpN * 32 + (lane & 3) * 2;

    prefetch_B_half(sb, imgV, h0);
    prefetch_A_sp(sb, g_bfA[0][0], g_bfA[0][1], n0);
#pragma unroll 1
    for (int c = 0; c < 3; ++c) {
        cpa_wait<0>();
        __syncthreads();
        float acc[2][4][4];
        zero_acc_h(acc);
        gemm3_half(sb, warpM, warpN, lane, acc);
        __syncthreads();
        if (c < 2) prefetch_A_sp(sb, g_bfA[c + 1][0], g_bfA[c + 1][1], n0);
#pragma unroll
        for (int mt = 0; mt < 2; ++mt)
#pragma unroll
            for (int hrow = 0; hrow < 2; ++hrow) {
                int n = n0 + r0 + mt * 16 + hrow * 8;
                if (n < N) {
                    float* o = out + (size_t)n * FDIM * 3 + c;
#pragma unroll
                    for (int nidx = 0; nidx < 4; ++nidx) {
                        int a = c0b + nidx * 8;
                        o[(size_t)a * 3]       = acc[mt][nidx][hrow * 2 + 0];
                        o[(size_t)(a + 1) * 3] = acc[mt][nidx][hrow * 2 + 1];
                    }
                }
            }
    }
}

// ================= combine: writes pre-split ms (g_msS) + mv (g_bfA, reuse) =================
__global__ void __launch_bounds__(FDIM) combine_kernel(
    const float* __restrict__ T0, const float* __restrict__ T1,
    const float* __restrict__ T2, const float* __restrict__ T3,
    const float* __restrict__ M0, const float* __restrict__ M1,
    const float* __restrict__ M2, const float* __restrict__ M3, int N) {
    int n = blockIdx.x;
    __shared__ float st[40];
    int tid = threadIdx.x;
    if (tid == 0) st[0] = T0[n];
    if (tid < 3) st[1 + tid] = T1[(size_t)n * 3 + tid];
    if (tid >= 32 && tid < 41) st[4 + tid - 32] = T2[(size_t)n * 9 + (tid - 32)];
    if (tid >= 64 && tid < 91) st[13 + tid - 64] = T3[(size_t)n * 27 + (tid - 64)];
    __syncthreads();

    float t0 = st[0];
    float t1[3], t2[9], t3[27];
#pragma unroll
    for (int k = 0; k < 3; ++k) t1[k] = st[1 + k];
#pragma unroll
    for (int k = 0; k < 9; ++k) t2[k] = st[4 + k];
#pragma unroll
    for (int k = 0; k < 27; ++k) t3[k] = st[13 + k];

    size_t base = (size_t)n * FDIM + tid;
    float m0 = M0[base];
    float m1[3], m2[3], m3[3];
#pragma unroll
    for (int c = 0; c < 3; ++c) {
        m1[c] = M1[base + (size_t)c * PLANE];
        m2[c] = M2[base + (size_t)c * PLANE];
        m3[c] = M3[base + (size_t)c * PLANE];
    }

    float s = t0 * m0;
#pragma unroll
    for (int i = 0; i < 3; ++i) s += m1[i] * t1[i];
#pragma unroll
    for (int i = 0; i < 3; ++i)
#pragma unroll
        for (int j = 0; j < 3; ++j) s += m2[i] * m2[j] * t2[i * 3 + j];
#pragma unroll
    for (int i = 0; i < 3; ++i) {
        float mi = m3[i];
#pragma unroll
        for (int j = 0; j < 3; ++j) {
            float mij = mi * m3[j];
#pragma unroll
            for (int k = 0; k < 3; ++k) s += mij * m3[k] * t3[i * 9 + j * 3 + k];
        }
    }
    {
        unsigned short h, l;
        split1(s, h, l);
        g_msS[0][base] = *(__nv_bfloat16*)&h;
        g_msS[1][base] = *(__nv_bfloat16*)&l;
    }

#pragma unroll
    for (int i = 0; i < 3; ++i) {
        float v = t1[i] * m0;
#pragma unroll
        for (int j = 0; j < 3; ++j) v += t2[i * 3 + j] * m1[j];
#pragma unroll
        for (int j = 0; j < 3; ++j)
#pragma unroll
            for (int k = 0; k < 3; ++k) v += t3[i * 9 + j * 3 + k] * m2[j] * m2[k];
        unsigned short h, l;
        split1(v, h, l);
        g_bfA[i][0][base] = *(__nv_bfloat16*)&h;   // mu planes dead; reuse as mv
        g_bfA[i][1][base] = *(__nv_bfloat16*)&l;
    }
}

// ================= launch =================
extern "C" void kernel_launch(void* const* d_in, const int* in_sizes, int n_in,
                              void* d_out, int out_size) {
    const float* feat = (const float*)d_in[0];
    const float* mu   = (const float*)d_in[1];
    const float* T0   = (const float*)d_in[2];
    const float* T1   = (const float*)d_in[3];
    const float* T2   = (const float*)d_in[4];
    const float* T3   = (const float*)d_in[5];
    const float* Wq1  = (const float*)d_in[6];
    const float* bq1  = (const float*)d_in[7];
    const float* Wq2  = (const float*)d_in[8];
    const float* bq2  = (const float*)d_in[9];
    const float* WT1  = (const float*)d_in[10];
    const float* WT2  = (const float*)d_in[11];
    const float* WT3  = (const float*)d_in[12];
    const float* Ws1  = (const float*)d_in[13];
    const float* bs1  = (const float*)d_in[14];
    const float* Ws2  = (const float*)d_in[15];
    const float* bs2  = (const float*)d_in[16];
    const float* Wv   = (const float*)d_in[17];

    int N = in_sizes[0] / FDIM;
    if (N > MAXN) N = MAXN;

    float* out = (float*)d_out;
    float* ms_out = out;
    float* mv_out = out + (size_t)N * FDIM;

    cudaFuncSetAttribute(dense1_feat_kernel, cudaFuncAttributeMaxDynamicSharedMemorySize, SMSZH);
    cudaFuncSetAttribute(dense1_sp_kernel,   cudaFuncAttributeMaxDynamicSharedMemorySize, SMSZH);
    cudaFuncSetAttribute(dense2b_kernel,     cudaFuncAttributeMaxDynamicSharedMemorySize, SMSZH);
    cudaFuncSetAttribute(muproj_split_kernel, cudaFuncAttributeMaxDynamicSharedMemorySize, SMSZH);
    cudaFuncSetAttribute(vproj_split_kernel,  cudaFuncAttributeMaxDynamicSharedMemorySize, SMSZH);

    float *pM0, *pM1, *pM2, *pM3;
    __nv_bfloat16 *pW, *pTmp, *pMs;
    cudaGetSymbolAddress((void**)&pM0, g_M0);
    cudaGetSymbolAddress((void**)&pM1, g_M1);
    cudaGetSymbolAddress((void**)&pM2, g_M2);
    cudaGetSymbolAddress((void**)&pM3, g_M3);
    cudaGetSymbolAddress((void**)&pW,  g_Wimg);
    cudaGetSymbolAddress((void**)&pTmp, g_tmp);
    cudaGetSymbolAddress((void**)&pMs,  g_msS);

    WPtrs wp;
    wp.p[0] = Wq1; wp.p[1] = Wq2; wp.p[2] = WT1; wp.p[3] = WT2;
    wp.p[4] = WT3; wp.p[5] = Ws1; wp.p[6] = Ws2; wp.p[7] = Wv;
    prep_weights<<<8, 256>>>(wp);
    mu_split_kernel<<<592, 256>>>(mu, N);

    int nb = (N + TILE - 1) / TILE;
    dense1_feat_kernel<<<2 * nb, NTH, SMSZH>>>(feat, pW + 0 * 32768, bq1, N);
    dense2b_kernel<<<2 * nb, NTH, SMSZH>>>(pTmp, pTmp + PLANEP, pW + 1 * 32768, bq2, pM0, N);
    muproj_split_kernel<<<2 * nb, NTH, SMSZH>>>(pW + 2 * 32768, pW + 3 * 32768, pW + 4 * 32768,
                                                pM1, pM2, pM3, N);
    combine_kernel<<<N, FDIM>>>(T0, T1, T2, T3, pM0, pM1, pM2, pM3, N);
    dense1_sp_kernel<<<2 * nb, NTH, SMSZH>>>(pMs, pMs + PLANEP, pW + 5 * 32768, bs1, N);
    dense2b_kernel<<<2 * nb, NTH, SMSZH>>>(pTmp, pTmp + PLANEP, pW + 6 * 32768, bs2, ms_out, N);
    vproj_split_kernel<<<2 * nb, NTH, SMSZH>>>(pW + 7 * 32768, mv_out, N);
}